// round 6
// baseline (speedup 1.0000x reference)
#include <cuda_runtime.h>
#include <cuda_bf16.h>
#include <math.h>
#include <stdint.h>

#define SEQ   2048
#define DIM   4096
#define NH    32
#define NKV   8
#define HD    128
#define KVD   1024
#define SCALE 0.08838834764831845f

// ---------------- scratch ----------------------------------------------------
__device__ float g_q[SEQ * DIM];
__device__ float g_k[SEQ * KVD];
__device__ float g_v[SEQ * KVD];
__device__ float g_att[SEQ * DIM];

// int8 limbs + scales for GEMMs
__device__ int8_t g_x1[SEQ * DIM],  g_x2[SEQ * DIM];
__device__ int8_t g_at1[SEQ * DIM], g_at2[SEQ * DIM];
__device__ int8_t g_wq1[DIM * DIM], g_wq2[DIM * DIM];
__device__ int8_t g_wk1[KVD * DIM], g_wk2[KVD * DIM];
__device__ int8_t g_wv1[KVD * DIM], g_wv2[KVD * DIM];
__device__ int8_t g_wo1[DIM * DIM], g_wo2[DIM * DIM];
__device__ float g_sa_x[SEQ], g_sa_at[SEQ];
__device__ float g_sb_q[DIM], g_sb_k[KVD], g_sb_v[KVD], g_sb_o[DIM];

// bf16 split Q/K/V for attention (Q pre-scaled, RoPE applied)
__device__ __nv_bfloat16 g_qs_hi[SEQ * DIM], g_qs_lo[SEQ * DIM];
__device__ __nv_bfloat16 g_ks_hi[SEQ * KVD], g_ks_lo[SEQ * KVD];
__device__ __nv_bfloat16 g_vs_hi[SEQ * KVD], g_vs_lo[SEQ * KVD];

// ---------------- PTX helpers (baseline PTX only) -----------------------------
__device__ __forceinline__ uint32_t smem_u32(const void* p) {
    uint32_t a;
    asm("{ .reg .u64 t; cvta.to.shared.u64 t, %1; cvt.u32.u64 %0, t; }"
        : "=r"(a) : "l"(p));
    return a;
}
#define CP_ASYNC16(dst, src) \
    asm volatile("cp.async.cg.shared.global [%0], [%1], 16;" :: "r"(dst), "l"(src) : "memory")
#define CP_COMMIT()  asm volatile("cp.async.commit_group;" ::: "memory")
#define CP_WAIT(n)   asm volatile("cp.async.wait_group %0;" :: "n"(n) : "memory")

#define LDSM_X4(r, addr)                                                      \
    asm volatile("ldmatrix.sync.aligned.m8n8.x4.shared.b16 {%0,%1,%2,%3}, [%4];" \
        : "=r"((r)[0]), "=r"((r)[1]), "=r"((r)[2]), "=r"((r)[3]) : "r"(addr))
#define LDSM_X4_T(r, addr)                                                    \
    asm volatile("ldmatrix.sync.aligned.m8n8.x4.trans.shared.b16 {%0,%1,%2,%3}, [%4];" \
        : "=r"((r)[0]), "=r"((r)[1]), "=r"((r)[2]), "=r"((r)[3]) : "r"(addr))

#define MMA_BF16(d, a, b0, b1)                                                \
    asm volatile("mma.sync.aligned.m16n8k16.row.col.f32.bf16.bf16.f32 "       \
        "{%0,%1,%2,%3}, {%4,%5,%6,%7}, {%8,%9}, {%0,%1,%2,%3};"               \
        : "+f"((d)[0]), "+f"((d)[1]), "+f"((d)[2]), "+f"((d)[3])              \
        : "r"((a)[0]), "r"((a)[1]), "r"((a)[2]), "r"((a)[3]), "r"(b0), "r"(b1))

#define MMA_S8(d, a, b0, b1)                                                  \
    asm volatile("mma.sync.aligned.m16n8k32.row.col.s32.s8.s8.s32 "           \
        "{%0,%1,%2,%3}, {%4,%5,%6,%7}, {%8,%9}, {%0,%1,%2,%3};"               \
        : "+r"((d)[0]), "+r"((d)[1]), "+r"((d)[2]), "+r"((d)[3])              \
        : "r"((a)[0]), "r"((a)[1]), "r"((a)[2]), "r"((a)[3]), "r"(b0), "r"(b1))

__device__ __forceinline__ uint32_t pack_bf16x2(float lo, float hi) {
    __nv_bfloat162 p = __float22bfloat162_rn(make_float2(lo, hi));
    return *(uint32_t*)&p;
}

// ---------------- quantization preprocessing ----------------------------------
__global__ void rowmax_kernel(const float* __restrict__ in,
                              float* __restrict__ sa, int K)
{
    __shared__ float red[4];
    const float* p = in + (size_t)blockIdx.x * K;
    float m = 0.f;
    for (int i = threadIdx.x * 4; i < K; i += blockDim.x * 4) {
        float4 v = *(const float4*)(p + i);
        m = fmaxf(m, fmaxf(fmaxf(fabsf(v.x), fabsf(v.y)),
                           fmaxf(fabsf(v.z), fabsf(v.w))));
    }
#pragma unroll
    for (int o = 16; o; o >>= 1) m = fmaxf(m, __shfl_xor_sync(~0u, m, o));
    if ((threadIdx.x & 31) == 0) red[threadIdx.x >> 5] = m;
    __syncthreads();
    if (threadIdx.x == 0) {
        m = fmaxf(fmaxf(red[0], red[1]), fmaxf(red[2], red[3]));
        sa[blockIdx.x] = fmaxf(m, 1e-20f) * (1.f / 127.f);
    }
}

// quantize activations: 2-limb int8 (per-row scale), one thread = 4 elements
__global__ void aquant_kernel(const float* __restrict__ in,
                              const float* __restrict__ sa,
                              int8_t* __restrict__ q1, int8_t* __restrict__ q2,
                              int K4)
{
    int i = blockIdx.x * blockDim.x + threadIdx.x;
    int row = i / K4;
    float inv = 1.f / sa[row];
    float4 v = ((const float4*)in)[i];
    float r0 = v.x * inv, r1 = v.y * inv, r2 = v.z * inv, r3 = v.w * inv;
    float h0 = rintf(r0), h1 = rintf(r1), h2 = rintf(r2), h3 = rintf(r3);
    ((char4*)q1)[i] = make_char4((int)h0, (int)h1, (int)h2, (int)h3);
    ((char4*)q2)[i] = make_char4((int)rintf((r0 - h0) * 128.f),
                                 (int)rintf((r1 - h1) * 128.f),
                                 (int)rintf((r2 - h2) * 128.f),
                                 (int)rintf((r3 - h3) * 128.f));
}

// per-column abs-max of W[K,N] -> sb[N]
__global__ void colmax_kernel(const float* __restrict__ B,
                              float* __restrict__ sb, int K, int N)
{
    int n = blockIdx.x * blockDim.x + threadIdx.x;
    float m = 0.f;
    for (int k = 0; k < K; k++) m = fmaxf(m, fabsf(B[(size_t)k * N + n]));
    sb[n] = fmaxf(m, 1e-20f) * (1.f / 127.f);
}

// transpose + quantize: W[K,N] fp32 -> WT limbs [N,K] int8
__global__ void wtquant_kernel(const float* __restrict__ B,
                               const float* __restrict__ sb,
                               int8_t* __restrict__ T1, int8_t* __restrict__ T2,
                               int K, int N)
{
    __shared__ float tile[32][33];
    int n0 = blockIdx.x * 32, k0 = blockIdx.y * 32;
    int tx = threadIdx.x, ty = threadIdx.y;
#pragma unroll
    for (int i = 0; i < 32; i += 8)
        tile[ty + i][tx] = B[(size_t)(k0 + ty + i) * N + n0 + tx];
    __syncthreads();
#pragma unroll
    for (int i = 0; i < 32; i += 8) {
        int n = n0 + ty + i;
        float inv = 1.f / sb[n];
        float v = tile[tx][ty + i] * inv;
        float h = rintf(v);
        size_t o = (size_t)n * K + k0 + tx;
        T1[o] = (int8_t)(int)h;
        T2[o] = (int8_t)(int)rintf((v - h) * 128.f);
    }
}

// ---------------- int8 2-limb IMMA GEMM ----------------------------------------
// C[M,N] = sa[m]*sb[n]*(A1B1 + (A1B2+A2B1)/128); A limbs [M,K], B limbs [N,K].
// CTA 128x128, BK=64, 8 warps 2x4 (warp tile 64x32).
#define ITSTR  80                         // smem row stride bytes (64 s8 + pad)
#define ITB    (128 * ITSTR)              // 10240 B per tile
#define IMMA_SMEM (2 * 4 * ITB)           // 81920 B

__global__ __launch_bounds__(256, 1) void gemm_imma(
    const int8_t* __restrict__ A1, const int8_t* __restrict__ A2,
    const int8_t* __restrict__ B1, const int8_t* __restrict__ B2,
    const float* __restrict__ sa, const float* __restrict__ sb,
    float* __restrict__ C, int M, int N, int K)
{
    extern __shared__ int8_t smi[];
    const uint32_t sbase = smem_u32(smi);
    const int t = threadIdx.x, lane = t & 31, w = t >> 5;
    const int wm = w & 1, wn = w >> 1;
    const int m0 = blockIdx.y << 7, n0 = blockIdx.x << 7;

    const int8_t* srcs[4] = { A1 + (size_t)m0 * K, A2 + (size_t)m0 * K,
                              B1 + (size_t)n0 * K, B2 + (size_t)n0 * K };

    int acc0[4][4][4], acc1[4][4][4];
#pragma unroll
    for (int a = 0; a < 4; a++)
#pragma unroll
        for (int b = 0; b < 4; b++)
#pragma unroll
            for (int c = 0; c < 4; c++) { acc0[a][b][c] = 0; acc1[a][b][c] = 0; }

    // prologue: buffer 0 (each tile: 128 rows x 64 s8 = 512 x 16B chunks)
#pragma unroll
    for (int tile = 0; tile < 4; tile++)
#pragma unroll
        for (int p = 0; p < 2; p++) {
            int chunk = t + p * 256;
            int row = chunk >> 2, c = chunk & 3;
            CP_ASYNC16(sbase + tile * ITB + row * ITSTR + c * 16,
                       srcs[tile] + (size_t)row * K + c * 16);
        }
    CP_COMMIT();

    const int niter = K >> 6;
    for (int i = 0; i < niter; i++) {
        const int b = i & 1;
        if (i + 1 < niter) {
            const int nb = b ^ 1;
            const size_t koff = (size_t)(i + 1) << 6;
#pragma unroll
            for (int tile = 0; tile < 4; tile++)
#pragma unroll
                for (int p = 0; p < 2; p++) {
                    int chunk = t + p * 256;
                    int row = chunk >> 2, c = chunk & 3;
                    CP_ASYNC16(sbase + (nb * 4 + tile) * ITB + row * ITSTR + c * 16,
                               srcs[tile] + (size_t)row * K + koff + c * 16);
                }
            CP_COMMIT();
            CP_WAIT(1);
        } else {
            CP_WAIT(0);
        }
        __syncthreads();

        const uint32_t TA1 = sbase + (b * 4 + 0) * ITB;
        const uint32_t TA2 = sbase + (b * 4 + 1) * ITB;
        const uint32_t TB1 = sbase + (b * 4 + 2) * ITB;
        const uint32_t TB2 = sbase + (b * 4 + 3) * ITB;

#pragma unroll
        for (int ks = 0; ks < 2; ks++) {
            const int koffB = ks * 32 + (lane >> 4) * 16;
            uint32_t a1f[4][4], a2f[4][4], b1f[2][4], b2f[2][4];
#pragma unroll
            for (int mt = 0; mt < 4; mt++) {
                uint32_t off = (uint32_t)(wm * 64 + mt * 16 + (lane & 15)) * ITSTR + koffB;
                LDSM_X4(a1f[mt], TA1 + off);
                LDSM_X4(a2f[mt], TA2 + off);
            }
#pragma unroll
            for (int np = 0; np < 2; np++) {
                uint32_t off = (uint32_t)(wn * 32 + np * 16 + (lane & 15)) * ITSTR + koffB;
                LDSM_X4(b1f[np], TB1 + off);
                LDSM_X4(b2f[np], TB2 + off);
            }
            // main products, then the two correction families (independent chains)
#pragma unroll
            for (int mt = 0; mt < 4; mt++)
#pragma unroll
                for (int nt = 0; nt < 4; nt++) {
                    const int np = nt >> 1, sel = nt & 1;
                    MMA_S8(acc0[mt][nt], a1f[mt], b1f[np][sel], b1f[np][sel + 2]);
                }
#pragma unroll
            for (int mt = 0; mt < 4; mt++)
#pragma unroll
                for (int nt = 0; nt < 4; nt++) {
                    const int np = nt >> 1, sel = nt & 1;
                    MMA_S8(acc1[mt][nt], a1f[mt], b2f[np][sel], b2f[np][sel + 2]);
                }
#pragma unroll
            for (int mt = 0; mt < 4; mt++)
#pragma unroll
                for (int nt = 0; nt < 4; nt++) {
                    const int np = nt >> 1, sel = nt & 1;
                    MMA_S8(acc1[mt][nt], a2f[mt], b1f[np][sel], b1f[np][sel + 2]);
                }
        }
        __syncthreads();
    }

    // epilogue: dequantize and store
#pragma unroll
    for (int mt = 0; mt < 4; mt++) {
        const int r = m0 + wm * 64 + mt * 16 + (lane >> 2);
        const float sar0 = sa[r], sar1 = sa[r + 8];
#pragma unroll
        for (int nt = 0; nt < 4; nt++) {
            const int c = n0 + wn * 32 + nt * 8 + (lane & 3) * 2;
            const float2 sbv = *(const float2*)(sb + c);
            float v0 = ((float)acc0[mt][nt][0] + (float)acc1[mt][nt][0] * 0.0078125f);
            float v1 = ((float)acc0[mt][nt][1] + (float)acc1[mt][nt][1] * 0.0078125f);
            float v2 = ((float)acc0[mt][nt][2] + (float)acc1[mt][nt][2] * 0.0078125f);
            float v3 = ((float)acc0[mt][nt][3] + (float)acc1[mt][nt][3] * 0.0078125f);
            *(float2*)(C + (size_t)r * N + c) =
                make_float2(v0 * sar0 * sbv.x, v1 * sar0 * sbv.y);
            *(float2*)(C + (size_t)(r + 8) * N + c) =
                make_float2(v2 * sar1 * sbv.x, v3 * sar1 * sbv.y);
        }
    }
}

// ---------------- fused RoPE + scale + bf16 split for Q and K -----------------
__global__ void rope_split_kernel(
    const float* __restrict__ q, const float* __restrict__ k,
    const float* __restrict__ fc, const float* __restrict__ fs,
    __nv_bfloat16* __restrict__ qh, __nv_bfloat16* __restrict__ ql,
    __nv_bfloat16* __restrict__ kh, __nv_bfloat16* __restrict__ kl)
{
    int idx = blockIdx.x * blockDim.x + threadIdx.x;
    const int qn = SEQ * NH * (HD / 2);
    const int kn = SEQ * NKV * (HD / 2);
    float o1, o2;
    size_t off;
    __nv_bfloat16 *ph, *pl;
    if (idx < qn) {
        int s = idx / (NH * 64);
        int rem = idx - s * (NH * 64);
        int h = rem >> 6, i = rem & 63;
        float c = fc[s * 64 + i], sn = fs[s * 64 + i];
        off = (size_t)s * DIM + h * HD + 2 * i;
        float t1 = q[off], t2 = q[off + 1];
        o1 = (t1 * c - t2 * sn) * SCALE;
        o2 = (t1 * sn + t2 * c) * SCALE;
        ph = qh; pl = ql;
    } else if (idx < qn + kn) {
        int j = idx - qn;
        int s = j / (NKV * 64);
        int rem = j - s * (NKV * 64);
        int h = rem >> 6, i = rem & 63;
        float c = fc[s * 64 + i], sn = fs[s * 64 + i];
        off = (size_t)s * KVD + h * HD + 2 * i;
        float t1 = k[off], t2 = k[off + 1];
        o1 = t1 * c - t2 * sn;
        o2 = t1 * sn + t2 * c;
        ph = kh; pl = kl;
    } else return;
    __nv_bfloat16 h1 = __float2bfloat16(o1);
    __nv_bfloat16 h2 = __float2bfloat16(o2);
    __nv_bfloat162 hp; hp.x = h1; hp.y = h2;
    __nv_bfloat162 lp;
    lp.x = __float2bfloat16(o1 - __bfloat162float(h1));
    lp.y = __float2bfloat16(o2 - __bfloat162float(h2));
    *(__nv_bfloat162*)(ph + off) = hp;
    *(__nv_bfloat162*)(pl + off) = lp;
}

// ---------------- elementwise split fp32 -> bf16 hi/lo (for V) ----------------
__global__ void split_kernel(const float* __restrict__ in,
                             __nv_bfloat16* __restrict__ hi,
                             __nv_bfloat16* __restrict__ lo, int n4)
{
    int i = blockIdx.x * blockDim.x + threadIdx.x;
    if (i >= n4) return;
    float4 v = ((const float4*)in)[i];
    __nv_bfloat16 h0 = __float2bfloat16(v.x);
    __nv_bfloat16 h1 = __float2bfloat16(v.y);
    __nv_bfloat16 h2 = __float2bfloat16(v.z);
    __nv_bfloat16 h3 = __float2bfloat16(v.w);
    __nv_bfloat162* hp = (__nv_bfloat162*)hi;
    __nv_bfloat162* lp = (__nv_bfloat162*)lo;
    __nv_bfloat162 a; a.x = h0; a.y = h1; hp[i * 2] = a;
    __nv_bfloat162 b; b.x = h2; b.y = h3; hp[i * 2 + 1] = b;
    __nv_bfloat162 c;
    c.x = __float2bfloat16(v.x - __bfloat162float(h0));
    c.y = __float2bfloat16(v.y - __bfloat162float(h1));
    lp[i * 2] = c;
    __nv_bfloat162 d;
    d.x = __float2bfloat16(v.z - __bfloat162float(h2));
    d.y = __float2bfloat16(v.w - __bfloat162float(h3));
    lp[i * 2 + 1] = d;
}

// ---------------- tensor-core flash attention (R5-proven; fp32 output) --------
#define AROWB 272
#define QT_B  (128 * AROWB)
#define KT_B  (64 * AROWB)
#define KVBUF (4 * KT_B)
#define ATT_SMEM (2 * QT_B + 2 * KVBUF)

__global__ __launch_bounds__(256) void attn_tc(
    const __nv_bfloat16* __restrict__ Qh, const __nv_bfloat16* __restrict__ Ql,
    const __nv_bfloat16* __restrict__ Kh, const __nv_bfloat16* __restrict__ Kl,
    const __nv_bfloat16* __restrict__ Vh, const __nv_bfloat16* __restrict__ Vl,
    float* __restrict__ O)
{
    extern __shared__ char smc[];
    const uint32_t sb  = smem_u32(smc);
    const int t = threadIdx.x, lane = t & 31, w = t >> 5;
    const int h = blockIdx.y, q0 = blockIdx.x << 7, kvh = h >> 2;

    const uint32_t sQh = sb;
    const uint32_t sQl = sb + QT_B;
    const uint32_t sKV = sb + 2 * QT_B;

    {
        const __nv_bfloat16* qs[2] = { Qh, Ql };
        uint32_t qd[2] = { sQh, sQl };
#pragma unroll
        for (int tn = 0; tn < 2; tn++)
#pragma unroll
            for (int p = 0; p < 8; p++) {
                int chunk = t + p * 256;
                int row = chunk >> 4, c = chunk & 15;
                CP_ASYNC16(qd[tn] + row * AROWB + c * 16,
                           qs[tn] + (size_t)(q0 + row) * DIM + h * HD + c * 8);
            }
    }
    const __nv_bfloat16* kvsrc[4] = { Kh, Kl, Vh, Vl };
#pragma unroll
    for (int tn = 0; tn < 4; tn++)
#pragma unroll
        for (int p = 0; p < 4; p++) {
            int chunk = t + p * 256;
            int row = chunk >> 4, c = chunk & 15;
            CP_ASYNC16(sKV + tn * KT_B + row * AROWB + c * 16,
                       kvsrc[tn] + (size_t)row * KVD + kvh * HD + c * 8);
        }
    CP_COMMIT();

    float m0 = -INFINITY, m1 = -INFINITY, l0 = 0.f, l1 = 0.f;
    float oacc[16][4];
#pragma unroll
    for (int i = 0; i < 16; i++)
#pragma unroll
        for (int j = 0; j < 4; j++) oacc[i][j] = 0.f;

    const int NIT = SEQ / 64;
    for (int it = 0; it < NIT; it++) {
        CP_WAIT(0);
        __syncthreads();
        const uint32_t kvb = sKV + (it & 1) * KVBUF;
        if (it + 1 < NIT) {
            const uint32_t nb = sKV + ((it + 1) & 1) * KVBUF;
            const int k0n = (it + 1) * 64;
#pragma unroll
            for (int tn = 0; tn < 4; tn++)
#pragma unroll
                for (int p = 0; p < 4; p++) {
                    int chunk = t + p * 256;
                    int row = chunk >> 4, c = chunk & 15;
                    CP_ASYNC16(nb + tn * KT_B + row * AROWB + c * 16,
                               kvsrc[tn] + (size_t)(k0n + row) * KVD + kvh * HD + c * 8);
                }
            CP_COMMIT();
        }

        float sacc[8][4];
#pragma unroll
        for (int i = 0; i < 8; i++)
#pragma unroll
            for (int j = 0; j < 4; j++) sacc[i][j] = 0.f;

#pragma unroll
        for (int ks = 0; ks < 8; ks++) {
            const uint32_t aoff = (uint32_t)(16 * w + (lane & 15)) * AROWB
                                + ks * 32 + (lane >> 4) * 16;
            uint32_t ah[4], al[4];
            LDSM_X4(ah, sQh + aoff);
            LDSM_X4(al, sQl + aoff);
#pragma unroll
            for (int g = 0; g < 4; g++) {
                const uint32_t boff = (uint32_t)(g * 16 + (lane & 15)) * AROWB
                                    + ks * 32 + (lane >> 4) * 16;
                uint32_t bh[4], bl[4];
                LDSM_X4(bh, kvb + boff);
                LDSM_X4(bl, kvb + KT_B + boff);
#pragma unroll
                for (int sel = 0; sel < 2; sel++) {
                    MMA_BF16(sacc[2 * g + sel], ah, bh[sel], bh[sel + 2]);
                    MMA_BF16(sacc[2 * g + sel], ah, bl[sel], bl[sel + 2]);
                    MMA_BF16(sacc[2 * g + sel], al, bh[sel], bh[sel + 2]);
                }
            }
        }

        float mc0 = -INFINITY, mc1 = -INFINITY;
#pragma unroll
        for (int i = 0; i < 8; i++) {
            mc0 = fmaxf(mc0, fmaxf(sacc[i][0], sacc[i][1]));
            mc1 = fmaxf(mc1, fmaxf(sacc[i][2], sacc[i][3]));
        }
        mc0 = fmaxf(mc0, __shfl_xor_sync(0xffffffffu, mc0, 1));
        mc0 = fmaxf(mc0, __shfl_xor_sync(0xffffffffu, mc0, 2));
        mc1 = fmaxf(mc1, __shfl_xor_sync(0xffffffffu, mc1, 1));
        mc1 = fmaxf(mc1, __shfl_xor_sync(0xffffffffu, mc1, 2));
        const float mn0 = fmaxf(m0, mc0), mn1 = fmaxf(m1, mc1);
        const float alpha0 = __expf(m0 - mn0), alpha1 = __expf(m1 - mn1);
        m0 = mn0; m1 = mn1;
        float sum0 = 0.f, sum1 = 0.f;
#pragma unroll
        for (int i = 0; i < 8; i++) {
            sacc[i][0] = __expf(sacc[i][0] - mn0);
            sacc[i][1] = __expf(sacc[i][1] - mn0);
            sacc[i][2] = __expf(sacc[i][2] - mn1);
            sacc[i][3] = __expf(sacc[i][3] - mn1);
            sum0 += sacc[i][0] + sacc[i][1];
            sum1 += sacc[i][2] + sacc[i][3];
        }
        sum0 += __shfl_xor_sync(0xffffffffu, sum0, 1);
        sum0 += __shfl_xor_sync(0xffffffffu, sum0, 2);
        sum1 += __shfl_xor_sync(0xffffffffu, sum1, 1);
        sum1 += __shfl_xor_sync(0xffffffffu, sum1, 2);
        l0 = l0 * alpha0 + sum0;
        l1 = l1 * alpha1 + sum1;

#pragma unroll
        for (int i = 0; i < 16; i++) {
            oacc[i][0] *= alpha0; oacc[i][1] *= alpha0;
            oacc[i][2] *= alpha1; oacc[i][3] *= alpha1;
        }

        uint32_t pah[4][4], pal[4][4];
#pragma unroll
        for (int ks = 0; ks < 4; ks++) {
#pragma unroll
            for (int half = 0; half < 2; half++) {
                const int nt = 2 * ks + half;
                float e0 = sacc[nt][0], e1 = sacc[nt][1];
                float e2 = sacc[nt][2], e3 = sacc[nt][3];
                __nv_bfloat16 h0 = __float2bfloat16(e0);
                __nv_bfloat16 h1 = __float2bfloat16(e1);
                __nv_bfloat16 h2 = __float2bfloat16(e2);
                __nv_bfloat16 h3 = __float2bfloat16(e3);
                pah[ks][2 * half + 0] = pack_bf16x2(e0, e1);
                pah[ks][2 * half + 1] = pack_bf16x2(e2, e3);
                pal[ks][2 * half + 0] = pack_bf16x2(e0 - __bfloat162float(h0),
                                                    e1 - __bfloat162float(h1));
                pal[ks][2 * half + 1] = pack_bf16x2(e2 - __bfloat162float(h2),
                                                    e3 - __bfloat162float(h3));
            }
        }

#pragma unroll
        for (int ks = 0; ks < 4; ks++) {
#pragma unroll
            for (int g = 0; g < 8; g++) {
                const uint32_t voff = (uint32_t)(ks * 16 + (lane & 15)) * AROWB
                                    + (g * 16 + (lane >> 4) * 8) * 2;
                uint32_t vh[4], vl[4];
                LDSM_X4_T(vh, kvb + 2 * KT_B + voff);
                LDSM_X4_T(vl, kvb + 3 * KT_B + voff);
#pragma unroll
                for (int sel = 0; sel < 2; sel++) {
                    MMA_BF16(oacc[2 * g + sel], pah[ks], vh[2 * sel], vh[2 * sel + 1]);
                    MMA_BF16(oacc[2 * g + sel], pah[ks], vl[2 * sel], vl[2 * sel + 1]);
                    MMA_BF16(oacc[2 * g + sel], pal[ks], vh[2 * sel], vh[2 * sel + 1]);
                }
            }
        }
    }

    const float inv0 = 1.0f / l0, inv1 = 1.0f / l1;
    const int r0 = q0 + 16 * w + (lane >> 2);
    const int r1 = r0 + 8;
#pragma unroll
    for (int nt = 0; nt < 16; nt++) {
        const int col = h * HD + nt * 8 + (lane & 3) * 2;
        *(float2*)(O + (size_t)r0 * DIM + col) =
            make_float2(oacc[nt][0] * inv0, oacc[nt][1] * inv0);
        *(float2*)(O + (size_t)r1 * DIM + col) =
            make_float2(oacc[nt][2] * inv1, oacc[nt][3] * inv1);
    }
}

// ---------------- launch -------------------------------------------------------
extern "C" void kernel_launch(void* const* d_in, const int* in_sizes, int n_in,
                              void* d_out, int out_size)
{
    const float* x  = (const float*)d_in[0];
    const float* fc = (const float*)d_in[1];
    const float* fs = (const float*)d_in[2];
    const float* wq = (const float*)d_in[3];
    const float* wk = (const float*)d_in[4];
    const float* wv = (const float*)d_in[5];
    const float* wo = (const float*)d_in[6];
    float* out = (float*)d_out;

    float *q, *k, *v, *att;
    cudaGetSymbolAddress((void**)&q,   g_q);
    cudaGetSymbolAddress((void**)&k,   g_k);
    cudaGetSymbolAddress((void**)&v,   g_v);
    cudaGetSymbolAddress((void**)&att, g_att);

    int8_t *x1, *x2, *at1, *at2, *wq1, *wq2, *wk1, *wk2, *wv1, *wv2, *wo1, *wo2;
    float *sax, *saat, *sbq, *sbk, *sbv, *sbo;
    cudaGetSymbolAddress((void**)&x1,  g_x1);   cudaGetSymbolAddress((void**)&x2,  g_x2);
    cudaGetSymbolAddress((void**)&at1, g_at1);  cudaGetSymbolAddress((void**)&at2, g_at2);
    cudaGetSymbolAddress((void**)&wq1, g_wq1);  cudaGetSymbolAddress((void**)&wq2, g_wq2);
    cudaGetSymbolAddress((void**)&wk1, g_wk1);  cudaGetSymbolAddress((void**)&wk2, g_wk2);
    cudaGetSymbolAddress((void**)&wv1, g_wv1);  cudaGetSymbolAddress((void**)&wv2, g_wv2);
    cudaGetSymbolAddress((void**)&wo1, g_wo1);  cudaGetSymbolAddress((void**)&wo2, g_wo2);
    cudaGetSymbolAddress((void**)&sax, g_sa_x); cudaGetSymbolAddress((void**)&saat, g_sa_at);
    cudaGetSymbolAddress((void**)&sbq, g_sb_q); cudaGetSymbolAddress((void**)&sbk, g_sb_k);
    cudaGetSymbolAddress((void**)&sbv, g_sb_v); cudaGetSymbolAddress((void**)&sbo, g_sb_o);

    __nv_bfloat16 *qsh, *qsl, *ksh, *ksl, *vsh, *vsl;
    cudaGetSymbolAddress((void**)&qsh, g_qs_hi); cudaGetSymbolAddress((void**)&qsl, g_qs_lo);
    cudaGetSymbolAddress((void**)&ksh, g_ks_hi); cudaGetSymbolAddress((void**)&ksl, g_ks_lo);
    cudaGetSymbolAddress((void**)&vsh, g_vs_hi); cudaGetSymbolAddress((void**)&vsl, g_vs_lo);

    cudaFuncSetAttribute(gemm_imma,
                         cudaFuncAttributeMaxDynamicSharedMemorySize, IMMA_SMEM);
    cudaFuncSetAttribute(attn_tc,
                         cudaFuncAttributeMaxDynamicSharedMemorySize, ATT_SMEM);

    // quantize x and weights
    rowmax_kernel<<<SEQ, 128>>>(x, sax, DIM);
    aquant_kernel<<<SEQ * DIM / 4 / 256, 256>>>(x, sax, x1, x2, DIM / 4);
    colmax_kernel<<<DIM / 256, 256>>>(wq, sbq, DIM, DIM);
    colmax_kernel<<<KVD / 256, 256>>>(wk, sbk, DIM, KVD);
    colmax_kernel<<<KVD / 256, 256>>>(wv, sbv, DIM, KVD);
    colmax_kernel<<<DIM / 256, 256>>>(wo, sbo, DIM, DIM);
    wtquant_kernel<<<dim3(DIM / 32, DIM / 32), dim3(32, 8)>>>(wq, sbq, wq1, wq2, DIM, DIM);
    wtquant_kernel<<<dim3(KVD / 32, DIM / 32), dim3(32, 8)>>>(wk, sbk, wk1, wk2, DIM, KVD);
    wtquant_kernel<<<dim3(KVD / 32, DIM / 32), dim3(32, 8)>>>(wv, sbv, wv1, wv2, DIM, KVD);
    wtquant_kernel<<<dim3(DIM / 32, DIM / 32), dim3(32, 8)>>>(wo, sbo, wo1, wo2, DIM, DIM);

    // projections on IMMA
    gemm_imma<<<dim3(DIM / 128, SEQ / 128), 256, IMMA_SMEM>>>(
        x1, x2, wq1, wq2, sax, sbq, q, SEQ, DIM, DIM);
    gemm_imma<<<dim3(KVD / 128, SEQ / 128), 256, IMMA_SMEM>>>(
        x1, x2, wk1, wk2, sax, sbk, k, SEQ, KVD, DIM);
    gemm_imma<<<dim3(KVD / 128, SEQ / 128), 256, IMMA_SMEM>>>(
        x1, x2, wv1, wv2, sax, sbv, v, SEQ, KVD, DIM);

    // RoPE + scale + split for Q/K; split V (attention stays bf16x3)
    int nrope = SEQ * (NH + NKV) * (HD / 2);
    rope_split_kernel<<<(nrope + 255) / 256, 256>>>(q, k, fc, fs, qsh, qsl, ksh, ksl);
    split_kernel<<<(SEQ * KVD / 4 + 255) / 256, 256>>>(v, vsh, vsl, SEQ * KVD / 4);

    attn_tc<<<dim3(SEQ / 128, NH), 256, ATT_SMEM>>>(qsh, qsl, ksh, ksl, vsh, vsl, att);

    // quantize attention output, O-projection on IMMA
    rowmax_kernel<<<SEQ, 128>>>(att, saat, DIM);
    aquant_kernel<<<SEQ * DIM / 4 / 256, 256>>>(att, saat, at1, at2, DIM / 4);
    gemm_imma<<<dim3(DIM / 128, SEQ / 128), 256, IMMA_SMEM>>>(
        at1, at2, wo1, wo2, saat, sbo, out, SEQ, DIM, DIM);
}

// round 7
// speedup vs baseline: 4.1636x; 4.1636x over previous
#include <cuda_runtime.h>
#include <cuda_bf16.h>
#include <cuda_fp16.h>
#include <math.h>
#include <stdint.h>

#define SEQ   2048
#define DIM   4096
#define NH    32
#define NKV   8
#define HD    128
#define KVD   1024
#define SCALE 0.08838834764831845f

// ---------------- scratch ----------------------------------------------------
__device__ float g_q[SEQ * DIM];
__device__ float g_k[SEQ * KVD];
__device__ float g_v[SEQ * KVD];

// fp16 operands for GEMMs
__device__ __half g_xh[SEQ * DIM];
__device__ __half g_atth[SEQ * DIM];
__device__ __half g_wqT[DIM * DIM];
__device__ __half g_wkT[KVD * DIM];
__device__ __half g_wvT[KVD * DIM];
__device__ __half g_woT[DIM * DIM];

// bf16 split Q/K/V for attention (Q pre-scaled, RoPE applied)
__device__ __nv_bfloat16 g_qs_hi[SEQ * DIM], g_qs_lo[SEQ * DIM];
__device__ __nv_bfloat16 g_ks_hi[SEQ * KVD], g_ks_lo[SEQ * KVD];
__device__ __nv_bfloat16 g_vs_hi[SEQ * KVD], g_vs_lo[SEQ * KVD];

// ---------------- PTX helpers (baseline PTX only) -----------------------------
__device__ __forceinline__ uint32_t smem_u32(const void* p) {
    uint32_t a;
    asm("{ .reg .u64 t; cvta.to.shared.u64 t, %1; cvt.u32.u64 %0, t; }"
        : "=r"(a) : "l"(p));
    return a;
}
#define CP_ASYNC16(dst, src) \
    asm volatile("cp.async.cg.shared.global [%0], [%1], 16;" :: "r"(dst), "l"(src) : "memory")
#define CP_COMMIT()  asm volatile("cp.async.commit_group;" ::: "memory")
#define CP_WAIT(n)   asm volatile("cp.async.wait_group %0;" :: "n"(n) : "memory")

#define LDSM_X4(r, addr)                                                      \
    asm volatile("ldmatrix.sync.aligned.m8n8.x4.shared.b16 {%0,%1,%2,%3}, [%4];" \
        : "=r"((r)[0]), "=r"((r)[1]), "=r"((r)[2]), "=r"((r)[3]) : "r"(addr))
#define LDSM_X4_T(r, addr)                                                    \
    asm volatile("ldmatrix.sync.aligned.m8n8.x4.trans.shared.b16 {%0,%1,%2,%3}, [%4];" \
        : "=r"((r)[0]), "=r"((r)[1]), "=r"((r)[2]), "=r"((r)[3]) : "r"(addr))

#define MMA_BF16(d, a, b0, b1)                                                \
    asm volatile("mma.sync.aligned.m16n8k16.row.col.f32.bf16.bf16.f32 "       \
        "{%0,%1,%2,%3}, {%4,%5,%6,%7}, {%8,%9}, {%0,%1,%2,%3};"               \
        : "+f"((d)[0]), "+f"((d)[1]), "+f"((d)[2]), "+f"((d)[3])              \
        : "r"((a)[0]), "r"((a)[1]), "r"((a)[2]), "r"((a)[3]), "r"(b0), "r"(b1))

#define MMA_F16(d, a, b0, b1)                                                 \
    asm volatile("mma.sync.aligned.m16n8k16.row.col.f32.f16.f16.f32 "         \
        "{%0,%1,%2,%3}, {%4,%5,%6,%7}, {%8,%9}, {%0,%1,%2,%3};"               \
        : "+f"((d)[0]), "+f"((d)[1]), "+f"((d)[2]), "+f"((d)[3])              \
        : "r"((a)[0]), "r"((a)[1]), "r"((a)[2]), "r"((a)[3]), "r"(b0), "r"(b1))

__device__ __forceinline__ uint32_t pack_bf16x2(float lo, float hi) {
    __nv_bfloat162 p = __float22bfloat162_rn(make_float2(lo, hi));
    return *(uint32_t*)&p;
}

// ---------------- fp32 -> fp16 convert (elementwise) ---------------------------
__global__ void hconv_kernel(const float* __restrict__ in,
                             __half* __restrict__ out, int n4)
{
    int i = blockIdx.x * blockDim.x + threadIdx.x;
    if (i >= n4) return;
    float4 v = ((const float4*)in)[i];
    __half2* op = (__half2*)out;
    op[i * 2]     = __floats2half2_rn(v.x, v.y);
    op[i * 2 + 1] = __floats2half2_rn(v.z, v.w);
}

// ---------------- transpose + convert: W[K,N] fp32 -> WT[N,K] fp16 -------------
__global__ void tconv_kernel(const float* __restrict__ B,
                             __half* __restrict__ T, int K, int N)
{
    __shared__ float tile[32][33];
    int n0 = blockIdx.x * 32, k0 = blockIdx.y * 32;
    int tx = threadIdx.x, ty = threadIdx.y;
#pragma unroll
    for (int i = 0; i < 32; i += 8)
        tile[ty + i][tx] = B[(size_t)(k0 + ty + i) * N + n0 + tx];
    __syncthreads();
#pragma unroll
    for (int i = 0; i < 32; i += 8)
        T[(size_t)(n0 + ty + i) * K + k0 + tx] = __float2half_rn(tile[tx][ty + i]);
}

// ---------------- fp16 mma.sync GEMM: C[M,N] = A[M,K] @ B[N,K]^T ---------------
// 128x128 CTA tile, BK=32, single fp16 term, fp32 accum. 8 warps 2x4.
#define BK    32
#define TSTR  40
#define TILE_E (128 * TSTR)
#define GEMM_SMEM (2 * 2 * TILE_E * 2)     // 2 buf x 2 tiles x bytes = 40960

__global__ __launch_bounds__(256, 2) void gemm_h(
    const __half* __restrict__ A, const __half* __restrict__ B,
    float* __restrict__ C, int M, int N, int K)
{
    extern __shared__ __half smh[];
    const uint32_t sbase = smem_u32(smh);
    const int t = threadIdx.x, lane = t & 31, w = t >> 5;
    const int wm = w & 1, wn = w >> 1;
    const int m0 = blockIdx.y << 7, n0 = blockIdx.x << 7;

    const __half* srcs[2] = { A + (size_t)m0 * K, B + (size_t)n0 * K };

    float acc[4][4][4];
#pragma unroll
    for (int a = 0; a < 4; a++)
#pragma unroll
        for (int b = 0; b < 4; b++)
#pragma unroll
            for (int c = 0; c < 4; c++) acc[a][b][c] = 0.f;

    const int lr = t >> 2, lc = (t & 3) * 8;   // rows 0..63 (+64), col chunks

    // prologue: buffer 0
#pragma unroll
    for (int tile = 0; tile < 2; tile++) {
        const __half* s = srcs[tile];
        uint32_t d = sbase + (uint32_t)(tile * TILE_E) * 2;
        CP_ASYNC16(d + (lr * TSTR + lc) * 2,        s + (size_t)lr * K + lc);
        CP_ASYNC16(d + ((lr + 64) * TSTR + lc) * 2, s + (size_t)(lr + 64) * K + lc);
    }
    CP_COMMIT();

    const int niter = K / BK;
    for (int i = 0; i < niter; i++) {
        const int b = i & 1;
        if (i + 1 < niter) {
            const int nb = b ^ 1;
            const size_t koff = (size_t)(i + 1) * BK;
#pragma unroll
            for (int tile = 0; tile < 2; tile++) {
                const __half* s = srcs[tile] + koff;
                uint32_t d = sbase + (uint32_t)((nb * 2 + tile) * TILE_E) * 2;
                CP_ASYNC16(d + (lr * TSTR + lc) * 2,        s + (size_t)lr * K + lc);
                CP_ASYNC16(d + ((lr + 64) * TSTR + lc) * 2, s + (size_t)(lr + 64) * K + lc);
            }
            CP_COMMIT();
            CP_WAIT(1);
        } else {
            CP_WAIT(0);
        }
        __syncthreads();

        const uint32_t As = sbase + (uint32_t)((b * 2 + 0) * TILE_E) * 2;
        const uint32_t Bs = sbase + (uint32_t)((b * 2 + 1) * TILE_E) * 2;

#pragma unroll
        for (int ks = 0; ks < 2; ks++) {
            const int koff = ks * 16 + (lane >> 4) * 8;
            const int arow = wm * 64 + (lane & 15);
            const int brow = wn * 32 + (lane & 15);

            uint32_t af[4][4], bf[2][4];
#pragma unroll
            for (int mt = 0; mt < 4; mt++)
                LDSM_X4(af[mt], As + (uint32_t)((arow + mt * 16) * TSTR + koff) * 2);
#pragma unroll
            for (int np = 0; np < 2; np++)
                LDSM_X4(bf[np], Bs + (uint32_t)((brow + np * 16) * TSTR + koff) * 2);
#pragma unroll
            for (int mt = 0; mt < 4; mt++)
#pragma unroll
                for (int nt = 0; nt < 4; nt++) {
                    const int np = nt >> 1, sel = nt & 1;
                    MMA_F16(acc[mt][nt], af[mt], bf[np][sel], bf[np][sel + 2]);
                }
        }
        __syncthreads();
    }

#pragma unroll
    for (int mt = 0; mt < 4; mt++) {
        const int r = m0 + wm * 64 + mt * 16 + (lane >> 2);
#pragma unroll
        for (int nt = 0; nt < 4; nt++) {
            const int c = n0 + wn * 32 + nt * 8 + (lane & 3) * 2;
            *(float2*)(C + (size_t)r * N + c) =
                make_float2(acc[mt][nt][0], acc[mt][nt][1]);
            *(float2*)(C + (size_t)(r + 8) * N + c) =
                make_float2(acc[mt][nt][2], acc[mt][nt][3]);
        }
    }
}

// ---------------- fused RoPE + scale + bf16 split for Q and K -----------------
__global__ void rope_split_kernel(
    const float* __restrict__ q, const float* __restrict__ k,
    const float* __restrict__ fc, const float* __restrict__ fs,
    __nv_bfloat16* __restrict__ qh, __nv_bfloat16* __restrict__ ql,
    __nv_bfloat16* __restrict__ kh, __nv_bfloat16* __restrict__ kl)
{
    int idx = blockIdx.x * blockDim.x + threadIdx.x;
    const int qn = SEQ * NH * (HD / 2);
    const int kn = SEQ * NKV * (HD / 2);
    float o1, o2;
    size_t off;
    __nv_bfloat16 *ph, *pl;
    if (idx < qn) {
        int s = idx / (NH * 64);
        int rem = idx - s * (NH * 64);
        int h = rem >> 6, i = rem & 63;
        float c = fc[s * 64 + i], sn = fs[s * 64 + i];
        off = (size_t)s * DIM + h * HD + 2 * i;
        float t1 = q[off], t2 = q[off + 1];
        o1 = (t1 * c - t2 * sn) * SCALE;
        o2 = (t1 * sn + t2 * c) * SCALE;
        ph = qh; pl = ql;
    } else if (idx < qn + kn) {
        int j = idx - qn;
        int s = j / (NKV * 64);
        int rem = j - s * (NKV * 64);
        int h = rem >> 6, i = rem & 63;
        float c = fc[s * 64 + i], sn = fs[s * 64 + i];
        off = (size_t)s * KVD + h * HD + 2 * i;
        float t1 = k[off], t2 = k[off + 1];
        o1 = t1 * c - t2 * sn;
        o2 = t1 * sn + t2 * c;
        ph = kh; pl = kl;
    } else return;
    __nv_bfloat16 h1 = __float2bfloat16(o1);
    __nv_bfloat16 h2 = __float2bfloat16(o2);
    __nv_bfloat162 hp; hp.x = h1; hp.y = h2;
    __nv_bfloat162 lp;
    lp.x = __float2bfloat16(o1 - __bfloat162float(h1));
    lp.y = __float2bfloat16(o2 - __bfloat162float(h2));
    *(__nv_bfloat162*)(ph + off) = hp;
    *(__nv_bfloat162*)(pl + off) = lp;
}

// ---------------- elementwise split fp32 -> bf16 hi/lo (for V) ----------------
__global__ void split_kernel(const float* __restrict__ in,
                             __nv_bfloat16* __restrict__ hi,
                             __nv_bfloat16* __restrict__ lo, int n4)
{
    int i = blockIdx.x * blockDim.x + threadIdx.x;
    if (i >= n4) return;
    float4 v = ((const float4*)in)[i];
    __nv_bfloat16 h0 = __float2bfloat16(v.x);
    __nv_bfloat16 h1 = __float2bfloat16(v.y);
    __nv_bfloat16 h2 = __float2bfloat16(v.z);
    __nv_bfloat16 h3 = __float2bfloat16(v.w);
    __nv_bfloat162* hp = (__nv_bfloat162*)hi;
    __nv_bfloat162* lp = (__nv_bfloat162*)lo;
    __nv_bfloat162 a; a.x = h0; a.y = h1; hp[i * 2] = a;
    __nv_bfloat162 b; b.x = h2; b.y = h3; hp[i * 2 + 1] = b;
    __nv_bfloat162 c;
    c.x = __float2bfloat16(v.x - __bfloat162float(h0));
    c.y = __float2bfloat16(v.y - __bfloat162float(h1));
    lp[i * 2] = c;
    __nv_bfloat162 d;
    d.x = __float2bfloat16(v.z - __bfloat162float(h2));
    d.y = __float2bfloat16(v.w - __bfloat162float(h3));
    lp[i * 2 + 1] = d;
}

// ---------------- tensor-core flash attention (R5-proven; fp16 output) --------
#define AROWB 272
#define QT_B  (128 * AROWB)
#define KT_B  (64 * AROWB)
#define KVBUF (4 * KT_B)
#define ATT_SMEM (2 * QT_B + 2 * KVBUF)

__global__ __launch_bounds__(256) void attn_tc(
    const __nv_bfloat16* __restrict__ Qh, const __nv_bfloat16* __restrict__ Ql,
    const __nv_bfloat16* __restrict__ Kh, const __nv_bfloat16* __restrict__ Kl,
    const __nv_bfloat16* __restrict__ Vh, const __nv_bfloat16* __restrict__ Vl,
    __half* __restrict__ O)
{
    extern __shared__ char smc[];
    const uint32_t sb  = smem_u32(smc);
    const int t = threadIdx.x, lane = t & 31, w = t >> 5;
    const int h = blockIdx.y, q0 = blockIdx.x << 7, kvh = h >> 2;

    const uint32_t sQh = sb;
    const uint32_t sQl = sb + QT_B;
    const uint32_t sKV = sb + 2 * QT_B;

    {
        const __nv_bfloat16* qs[2] = { Qh, Ql };
        uint32_t qd[2] = { sQh, sQl };
#pragma unroll
        for (int tn = 0; tn < 2; tn++)
#pragma unroll
            for (int p = 0; p < 8; p++) {
                int chunk = t + p * 256;
                int row = chunk >> 4, c = chunk & 15;
                CP_ASYNC16(qd[tn] + row * AROWB + c * 16,
                           qs[tn] + (size_t)(q0 + row) * DIM + h * HD + c * 8);
            }
    }
    const __nv_bfloat16* kvsrc[4] = { Kh, Kl, Vh, Vl };
#pragma unroll
    for (int tn = 0; tn < 4; tn++)
#pragma unroll
        for (int p = 0; p < 4; p++) {
            int chunk = t + p * 256;
            int row = chunk >> 4, c = chunk & 15;
            CP_ASYNC16(sKV + tn * KT_B + row * AROWB + c * 16,
                       kvsrc[tn] + (size_t)row * KVD + kvh * HD + c * 8);
        }
    CP_COMMIT();

    float m0 = -INFINITY, m1 = -INFINITY, l0 = 0.f, l1 = 0.f;
    float oacc[16][4];
#pragma unroll
    for (int i = 0; i < 16; i++)
#pragma unroll
        for (int j = 0; j < 4; j++) oacc[i][j] = 0.f;

    const int NIT = SEQ / 64;
    for (int it = 0; it < NIT; it++) {
        CP_WAIT(0);
        __syncthreads();
        const uint32_t kvb = sKV + (it & 1) * KVBUF;
        if (it + 1 < NIT) {
            const uint32_t nb = sKV + ((it + 1) & 1) * KVBUF;
            const int k0n = (it + 1) * 64;
#pragma unroll
            for (int tn = 0; tn < 4; tn++)
#pragma unroll
                for (int p = 0; p < 4; p++) {
                    int chunk = t + p * 256;
                    int row = chunk >> 4, c = chunk & 15;
                    CP_ASYNC16(nb + tn * KT_B + row * AROWB + c * 16,
                               kvsrc[tn] + (size_t)(k0n + row) * KVD + kvh * HD + c * 8);
                }
            CP_COMMIT();
        }

        float sacc[8][4];
#pragma unroll
        for (int i = 0; i < 8; i++)
#pragma unroll
            for (int j = 0; j < 4; j++) sacc[i][j] = 0.f;

#pragma unroll
        for (int ks = 0; ks < 8; ks++) {
            const uint32_t aoff = (uint32_t)(16 * w + (lane & 15)) * AROWB
                                + ks * 32 + (lane >> 4) * 16;
            uint32_t ah[4], al[4];
            LDSM_X4(ah, sQh + aoff);
            LDSM_X4(al, sQl + aoff);
#pragma unroll
            for (int g = 0; g < 4; g++) {
                const uint32_t boff = (uint32_t)(g * 16 + (lane & 15)) * AROWB
                                    + ks * 32 + (lane >> 4) * 16;
                uint32_t bh[4], bl[4];
                LDSM_X4(bh, kvb + boff);
                LDSM_X4(bl, kvb + KT_B + boff);
#pragma unroll
                for (int sel = 0; sel < 2; sel++) {
                    MMA_BF16(sacc[2 * g + sel], ah, bh[sel], bh[sel + 2]);
                    MMA_BF16(sacc[2 * g + sel], ah, bl[sel], bl[sel + 2]);
                    MMA_BF16(sacc[2 * g + sel], al, bh[sel], bh[sel + 2]);
                }
            }
        }

        float mc0 = -INFINITY, mc1 = -INFINITY;
#pragma unroll
        for (int i = 0; i < 8; i++) {
            mc0 = fmaxf(mc0, fmaxf(sacc[i][0], sacc[i][1]));
            mc1 = fmaxf(mc1, fmaxf(sacc[i][2], sacc[i][3]));
        }
        mc0 = fmaxf(mc0, __shfl_xor_sync(0xffffffffu, mc0, 1));
        mc0 = fmaxf(mc0, __shfl_xor_sync(0xffffffffu, mc0, 2));
        mc1 = fmaxf(mc1, __shfl_xor_sync(0xffffffffu, mc1, 1));
        mc1 = fmaxf(mc1, __shfl_xor_sync(0xffffffffu, mc1, 2));
        const float mn0 = fmaxf(m0, mc0), mn1 = fmaxf(m1, mc1);
        const float alpha0 = __expf(m0 - mn0), alpha1 = __expf(m1 - mn1);
        m0 = mn0; m1 = mn1;
        float sum0 = 0.f, sum1 = 0.f;
#pragma unroll
        for (int i = 0; i < 8; i++) {
            sacc[i][0] = __expf(sacc[i][0] - mn0);
            sacc[i][1] = __expf(sacc[i][1] - mn0);
            sacc[i][2] = __expf(sacc[i][2] - mn1);
            sacc[i][3] = __expf(sacc[i][3] - mn1);
            sum0 += sacc[i][0] + sacc[i][1];
            sum1 += sacc[i][2] + sacc[i][3];
        }
        sum0 += __shfl_xor_sync(0xffffffffu, sum0, 1);
        sum0 += __shfl_xor_sync(0xffffffffu, sum0, 2);
        sum1 += __shfl_xor_sync(0xffffffffu, sum1, 1);
        sum1 += __shfl_xor_sync(0xffffffffu, sum1, 2);
        l0 = l0 * alpha0 + sum0;
        l1 = l1 * alpha1 + sum1;

#pragma unroll
        for (int i = 0; i < 16; i++) {
            oacc[i][0] *= alpha0; oacc[i][1] *= alpha0;
            oacc[i][2] *= alpha1; oacc[i][3] *= alpha1;
        }

        uint32_t pah[4][4], pal[4][4];
#pragma unroll
        for (int ks = 0; ks < 4; ks++) {
#pragma unroll
            for (int half = 0; half < 2; half++) {
                const int nt = 2 * ks + half;
                float e0 = sacc[nt][0], e1 = sacc[nt][1];
                float e2 = sacc[nt][2], e3 = sacc[nt][3];
                __nv_bfloat16 h0 = __float2bfloat16(e0);
                __nv_bfloat16 h1 = __float2bfloat16(e1);
                __nv_bfloat16 h2 = __float2bfloat16(e2);
                __nv_bfloat16 h3 = __float2bfloat16(e3);
                pah[ks][2 * half + 0] = pack_bf16x2(e0, e1);
                pah[ks][2 * half + 1] = pack_bf16x2(e2, e3);
                pal[ks][2 * half + 0] = pack_bf16x2(e0 - __bfloat162float(h0),
                                                    e1 - __bfloat162float(h1));
                pal[ks][2 * half + 1] = pack_bf16x2(e2 - __bfloat162float(h2),
                                                    e3 - __bfloat162float(h3));
            }
        }

#pragma unroll
        for (int ks = 0; ks < 4; ks++) {
#pragma unroll
            for (int g = 0; g < 8; g++) {
                const uint32_t voff = (uint32_t)(ks * 16 + (lane & 15)) * AROWB
                                    + (g * 16 + (lane >> 4) * 8) * 2;
                uint32_t vh[4], vl[4];
                LDSM_X4_T(vh, kvb + 2 * KT_B + voff);
                LDSM_X4_T(vl, kvb + 3 * KT_B + voff);
#pragma unroll
                for (int sel = 0; sel < 2; sel++) {
                    MMA_BF16(oacc[2 * g + sel], pah[ks], vh[2 * sel], vh[2 * sel + 1]);
                    MMA_BF16(oacc[2 * g + sel], pah[ks], vl[2 * sel], vl[2 * sel + 1]);
                    MMA_BF16(oacc[2 * g + sel], pal[ks], vh[2 * sel], vh[2 * sel + 1]);
                }
            }
        }
    }

    // epilogue: O /= l, write fp16 att directly (feeds fp16 O-proj GEMM)
    const float inv0 = 1.0f / l0, inv1 = 1.0f / l1;
    const int r0 = q0 + 16 * w + (lane >> 2);
    const int r1 = r0 + 8;
#pragma unroll
    for (int nt = 0; nt < 16; nt++) {
        const int col = h * HD + nt * 8 + (lane & 3) * 2;
        *(__half2*)(O + (size_t)r0 * DIM + col) =
            __floats2half2_rn(oacc[nt][0] * inv0, oacc[nt][1] * inv0);
        *(__half2*)(O + (size_t)r1 * DIM + col) =
            __floats2half2_rn(oacc[nt][2] * inv1, oacc[nt][3] * inv1);
    }
}

// ---------------- launch -------------------------------------------------------
extern "C" void kernel_launch(void* const* d_in, const int* in_sizes, int n_in,
                              void* d_out, int out_size)
{
    const float* x  = (const float*)d_in[0];
    const float* fc = (const float*)d_in[1];
    const float* fs = (const float*)d_in[2];
    const float* wq = (const float*)d_in[3];
    const float* wk = (const float*)d_in[4];
    const float* wv = (const float*)d_in[5];
    const float* wo = (const float*)d_in[6];
    float* out = (float*)d_out;

    float *q, *k, *v;
    cudaGetSymbolAddress((void**)&q, g_q);
    cudaGetSymbolAddress((void**)&k, g_k);
    cudaGetSymbolAddress((void**)&v, g_v);

    __half *xh, *atth, *wqT, *wkT, *wvT, *woT;
    cudaGetSymbolAddress((void**)&xh,   g_xh);
    cudaGetSymbolAddress((void**)&atth, g_atth);
    cudaGetSymbolAddress((void**)&wqT,  g_wqT);
    cudaGetSymbolAddress((void**)&wkT,  g_wkT);
    cudaGetSymbolAddress((void**)&wvT,  g_wvT);
    cudaGetSymbolAddress((void**)&woT,  g_woT);

    __nv_bfloat16 *qsh, *qsl, *ksh, *ksl, *vsh, *vsl;
    cudaGetSymbolAddress((void**)&qsh, g_qs_hi); cudaGetSymbolAddress((void**)&qsl, g_qs_lo);
    cudaGetSymbolAddress((void**)&ksh, g_ks_hi); cudaGetSymbolAddress((void**)&ksl, g_ks_lo);
    cudaGetSymbolAddress((void**)&vsh, g_vs_hi); cudaGetSymbolAddress((void**)&vsl, g_vs_lo);

    cudaFuncSetAttribute(gemm_h,
                         cudaFuncAttributeMaxDynamicSharedMemorySize, GEMM_SMEM);
    cudaFuncSetAttribute(attn_tc,
                         cudaFuncAttributeMaxDynamicSharedMemorySize, ATT_SMEM);

    // convert x + weights to fp16 (launches 1-5)
    hconv_kernel<<<(SEQ * DIM / 4 + 255) / 256, 256>>>(x, xh, SEQ * DIM / 4);
    tconv_kernel<<<dim3(DIM / 32, DIM / 32), dim3(32, 8)>>>(wq, wqT, DIM, DIM);
    tconv_kernel<<<dim3(KVD / 32, DIM / 32), dim3(32, 8)>>>(wk, wkT, DIM, KVD);
    tconv_kernel<<<dim3(KVD / 32, DIM / 32), dim3(32, 8)>>>(wv, wvT, DIM, KVD);
    tconv_kernel<<<dim3(DIM / 32, DIM / 32), dim3(32, 8)>>>(wo, woT, DIM, DIM);

    // projections (launch 6 = Q-proj -> ncu -s 5 captures this)
    gemm_h<<<dim3(DIM / 128, SEQ / 128), 256, GEMM_SMEM>>>(xh, wqT, q, SEQ, DIM, DIM);
    gemm_h<<<dim3(KVD / 128, SEQ / 128), 256, GEMM_SMEM>>>(xh, wkT, k, SEQ, KVD, DIM);
    gemm_h<<<dim3(KVD / 128, SEQ / 128), 256, GEMM_SMEM>>>(xh, wvT, v, SEQ, KVD, DIM);

    // RoPE + scale + split for Q/K; split V (attention stays bf16x3)
    int nrope = SEQ * (NH + NKV) * (HD / 2);
    rope_split_kernel<<<(nrope + 255) / 256, 256>>>(q, k, fc, fs, qsh, qsl, ksh, ksl);
    split_kernel<<<(SEQ * KVD / 4 + 255) / 256, 256>>>(v, vsh, vsl, SEQ * KVD / 4);

    // attention writes fp16 att directly
    attn_tc<<<dim3(SEQ / 128, NH), 256, ATT_SMEM>>>(qsh, qsl, ksh, ksl, vsh, vsl, atth);

    // output projection
    gemm_h<<<dim3(DIM / 128, SEQ / 128), 256, GEMM_SMEM>>>(atth, woT, out, SEQ, DIM, DIM);
}

// round 8
// speedup vs baseline: 4.2571x; 1.0224x over previous
#include <cuda_runtime.h>
#include <cuda_bf16.h>
#include <cuda_fp16.h>
#include <math.h>
#include <stdint.h>

#define SEQ   2048
#define DIM   4096
#define NH    32
#define NKV   8
#define HD    128
#define KVD   1024
#define QKVD  6144          // DIM + 2*KVD (merged q|k|v output)
#define SCALE 0.08838834764831845f

// ---------------- scratch ----------------------------------------------------
__device__ float g_qkv[SEQ * QKVD];        // merged q|k|v projection output

__device__ __half g_xh[SEQ * DIM];
__device__ __half g_atth[SEQ * DIM];
__device__ __half g_wqkvT[QKVD * DIM];     // [wq^T ; wk^T ; wv^T] rows
__device__ __half g_woT[DIM * DIM];

// bf16 split Q/K/V for attention (Q pre-scaled, RoPE applied)
__device__ __nv_bfloat16 g_qs_hi[SEQ * DIM], g_qs_lo[SEQ * DIM];
__device__ __nv_bfloat16 g_ks_hi[SEQ * KVD], g_ks_lo[SEQ * KVD];
__device__ __nv_bfloat16 g_vs_hi[SEQ * KVD], g_vs_lo[SEQ * KVD];

// ---------------- PTX helpers (baseline PTX only) -----------------------------
__device__ __forceinline__ uint32_t smem_u32(const void* p) {
    uint32_t a;
    asm("{ .reg .u64 t; cvta.to.shared.u64 t, %1; cvt.u32.u64 %0, t; }"
        : "=r"(a) : "l"(p));
    return a;
}
#define CP_ASYNC16(dst, src) \
    asm volatile("cp.async.cg.shared.global [%0], [%1], 16;" :: "r"(dst), "l"(src) : "memory")
#define CP_COMMIT()  asm volatile("cp.async.commit_group;" ::: "memory")
#define CP_WAIT(n)   asm volatile("cp.async.wait_group %0;" :: "n"(n) : "memory")

#define LDSM_X4(r, addr)                                                      \
    asm volatile("ldmatrix.sync.aligned.m8n8.x4.shared.b16 {%0,%1,%2,%3}, [%4];" \
        : "=r"((r)[0]), "=r"((r)[1]), "=r"((r)[2]), "=r"((r)[3]) : "r"(addr))
#define LDSM_X4_T(r, addr)                                                    \
    asm volatile("ldmatrix.sync.aligned.m8n8.x4.trans.shared.b16 {%0,%1,%2,%3}, [%4];" \
        : "=r"((r)[0]), "=r"((r)[1]), "=r"((r)[2]), "=r"((r)[3]) : "r"(addr))

#define MMA_BF16(d, a, b0, b1)                                                \
    asm volatile("mma.sync.aligned.m16n8k16.row.col.f32.bf16.bf16.f32 "       \
        "{%0,%1,%2,%3}, {%4,%5,%6,%7}, {%8,%9}, {%0,%1,%2,%3};"               \
        : "+f"((d)[0]), "+f"((d)[1]), "+f"((d)[2]), "+f"((d)[3])              \
        : "r"((a)[0]), "r"((a)[1]), "r"((a)[2]), "r"((a)[3]), "r"(b0), "r"(b1))

#define MMA_F16(d, a, b0, b1)                                                 \
    asm volatile("mma.sync.aligned.m16n8k16.row.col.f32.f16.f16.f32 "         \
        "{%0,%1,%2,%3}, {%4,%5,%6,%7}, {%8,%9}, {%0,%1,%2,%3};"               \
        : "+f"((d)[0]), "+f"((d)[1]), "+f"((d)[2]), "+f"((d)[3])              \
        : "r"((a)[0]), "r"((a)[1]), "r"((a)[2]), "r"((a)[3]), "r"(b0), "r"(b1))

__device__ __forceinline__ uint32_t pack_bf16x2(float lo, float hi) {
    __nv_bfloat162 p = __float22bfloat162_rn(make_float2(lo, hi));
    return *(uint32_t*)&p;
}

// ---------------- fp32 -> fp16 convert (elementwise) ---------------------------
__global__ void hconv_kernel(const float* __restrict__ in,
                             __half* __restrict__ out, int n4)
{
    int i = blockIdx.x * blockDim.x + threadIdx.x;
    if (i >= n4) return;
    float4 v = ((const float4*)in)[i];
    __half2* op = (__half2*)out;
    op[i * 2]     = __floats2half2_rn(v.x, v.y);
    op[i * 2 + 1] = __floats2half2_rn(v.z, v.w);
}

// ---------------- transpose + convert: W[K,N] fp32 -> WT[N,K] fp16 -------------
__global__ void tconv_kernel(const float* __restrict__ B,
                             __half* __restrict__ T, int K, int N)
{
    __shared__ float tile[32][33];
    int n0 = blockIdx.x * 32, k0 = blockIdx.y * 32;
    int tx = threadIdx.x, ty = threadIdx.y;
#pragma unroll
    for (int i = 0; i < 32; i += 8)
        tile[ty + i][tx] = B[(size_t)(k0 + ty + i) * N + n0 + tx];
    __syncthreads();
#pragma unroll
    for (int i = 0; i < 32; i += 8)
        T[(size_t)(n0 + ty + i) * K + k0 + tx] = __float2half_rn(tile[tx][ty + i]);
}

// ---------------- fp16 mma.sync GEMM: C[M,N] = A[M,K] @ B[N,K]^T ---------------
// CTA tile 128x256, BK=32, 8 warps 2x4 -> warp tile 64x64 (4x8 mma tiles).
#define BK     32
#define ASTR   40                       // smem row stride (halves)
#define A_E    (128 * ASTR)             // A tile: 5120 halves
#define B_E    (256 * ASTR)             // B tile: 10240 halves
#define BUF_E  (A_E + B_E)
#define GEMM_SMEM (2 * BUF_E * 2)       // 61440 bytes

__global__ __launch_bounds__(256, 1) void gemm_h(
    const __half* __restrict__ A, const __half* __restrict__ B,
    float* __restrict__ C, int M, int N, int K)
{
    extern __shared__ __half smh[];
    const uint32_t sbase = smem_u32(smh);
    const int t = threadIdx.x, lane = t & 31, w = t >> 5;
    const int wm = w & 1, wn = w >> 1;           // 2 x 4 warp grid
    const int m0 = blockIdx.y << 7, n0 = blockIdx.x << 8;

    const __half* srcA = A + (size_t)m0 * K;
    const __half* srcB = B + (size_t)n0 * K;

    float acc[4][8][4];
#pragma unroll
    for (int a = 0; a < 4; a++)
#pragma unroll
        for (int b = 0; b < 8; b++)
#pragma unroll
            for (int c = 0; c < 4; c++) acc[a][b][c] = 0.f;

    const int lr = t >> 2, lc = (t & 3) * 8;     // load row / col chunk (halves)

    // prologue: buffer 0
    {
        uint32_t dA = sbase;
        uint32_t dB = sbase + A_E * 2;
        CP_ASYNC16(dA + (lr * ASTR + lc) * 2,        srcA + (size_t)lr * K + lc);
        CP_ASYNC16(dA + ((lr + 64) * ASTR + lc) * 2, srcA + (size_t)(lr + 64) * K + lc);
#pragma unroll
        for (int rr = 0; rr < 4; rr++)
            CP_ASYNC16(dB + ((lr + rr * 64) * ASTR + lc) * 2,
                       srcB + (size_t)(lr + rr * 64) * K + lc);
    }
    CP_COMMIT();

    const int niter = K / BK;
    for (int i = 0; i < niter; i++) {
        const int b = i & 1;
        if (i + 1 < niter) {
            const int nb = b ^ 1;
            const size_t koff = (size_t)(i + 1) * BK;
            uint32_t dA = sbase + (uint32_t)(nb * BUF_E) * 2;
            uint32_t dB = dA + A_E * 2;
            CP_ASYNC16(dA + (lr * ASTR + lc) * 2,        srcA + (size_t)lr * K + koff + lc);
            CP_ASYNC16(dA + ((lr + 64) * ASTR + lc) * 2, srcA + (size_t)(lr + 64) * K + koff + lc);
#pragma unroll
            for (int rr = 0; rr < 4; rr++)
                CP_ASYNC16(dB + ((lr + rr * 64) * ASTR + lc) * 2,
                           srcB + (size_t)(lr + rr * 64) * K + koff + lc);
            CP_COMMIT();
            CP_WAIT(1);
        } else {
            CP_WAIT(0);
        }
        __syncthreads();

        const uint32_t As = sbase + (uint32_t)(b * BUF_E) * 2;
        const uint32_t Bs = As + A_E * 2;

#pragma unroll
        for (int ks = 0; ks < 2; ks++) {
            const int koff = ks * 16 + (lane >> 4) * 8;
            const int arow = wm * 64 + (lane & 15);
            const int brow = wn * 64 + (lane & 15);

            uint32_t af[4][4], bf[4][4];
#pragma unroll
            for (int mt = 0; mt < 4; mt++)
                LDSM_X4(af[mt], As + (uint32_t)((arow + mt * 16) * ASTR + koff) * 2);
#pragma unroll
            for (int np = 0; np < 4; np++)
                LDSM_X4(bf[np], Bs + (uint32_t)((brow + np * 16) * ASTR + koff) * 2);
#pragma unroll
            for (int mt = 0; mt < 4; mt++)
#pragma unroll
                for (int nt = 0; nt < 8; nt++) {
                    const int np = nt >> 1, sel = nt & 1;
                    MMA_F16(acc[mt][nt], af[mt], bf[np][sel], bf[np][sel + 2]);
                }
        }
        __syncthreads();
    }

#pragma unroll
    for (int mt = 0; mt < 4; mt++) {
        const int r = m0 + wm * 64 + mt * 16 + (lane >> 2);
#pragma unroll
        for (int nt = 0; nt < 8; nt++) {
            const int c = n0 + wn * 64 + nt * 8 + (lane & 3) * 2;
            *(float2*)(C + (size_t)r * N + c) =
                make_float2(acc[mt][nt][0], acc[mt][nt][1]);
            *(float2*)(C + (size_t)(r + 8) * N + c) =
                make_float2(acc[mt][nt][2], acc[mt][nt][3]);
        }
    }
}

// ---------------- fused RoPE + scale + bf16 split (reads merged qkv) ----------
__global__ void rope_split_kernel(
    const float* __restrict__ qkv,
    const float* __restrict__ fc, const float* __restrict__ fs,
    __nv_bfloat16* __restrict__ qh, __nv_bfloat16* __restrict__ ql,
    __nv_bfloat16* __restrict__ kh, __nv_bfloat16* __restrict__ kl)
{
    int idx = blockIdx.x * blockDim.x + threadIdx.x;
    const int qn = SEQ * NH * (HD / 2);
    const int kn = SEQ * NKV * (HD / 2);
    float o1, o2;
    size_t off_out;
    __nv_bfloat16 *ph, *pl;
    if (idx < qn) {
        int s = idx / (NH * 64);
        int rem = idx - s * (NH * 64);
        int h = rem >> 6, i = rem & 63;
        float c = fc[s * 64 + i], sn = fs[s * 64 + i];
        size_t off_in = (size_t)s * QKVD + h * HD + 2 * i;
        float t1 = qkv[off_in], t2 = qkv[off_in + 1];
        o1 = (t1 * c - t2 * sn) * SCALE;
        o2 = (t1 * sn + t2 * c) * SCALE;
        off_out = (size_t)s * DIM + h * HD + 2 * i;
        ph = qh; pl = ql;
    } else if (idx < qn + kn) {
        int j = idx - qn;
        int s = j / (NKV * 64);
        int rem = j - s * (NKV * 64);
        int h = rem >> 6, i = rem & 63;
        float c = fc[s * 64 + i], sn = fs[s * 64 + i];
        size_t off_in = (size_t)s * QKVD + DIM + h * HD + 2 * i;
        float t1 = qkv[off_in], t2 = qkv[off_in + 1];
        o1 = t1 * c - t2 * sn;
        o2 = t1 * sn + t2 * c;
        off_out = (size_t)s * KVD + h * HD + 2 * i;
        ph = kh; pl = kl;
    } else return;
    __nv_bfloat16 h1 = __float2bfloat16(o1);
    __nv_bfloat16 h2 = __float2bfloat16(o2);
    __nv_bfloat162 hp; hp.x = h1; hp.y = h2;
    __nv_bfloat162 lp;
    lp.x = __float2bfloat16(o1 - __bfloat162float(h1));
    lp.y = __float2bfloat16(o2 - __bfloat162float(h2));
    *(__nv_bfloat162*)(ph + off_out) = hp;
    *(__nv_bfloat162*)(pl + off_out) = lp;
}

// ---------------- strided split fp32 -> bf16 hi/lo (V from merged qkv) --------
__global__ void vsplit_kernel(const float* __restrict__ qkv,
                              __nv_bfloat16* __restrict__ hi,
                              __nv_bfloat16* __restrict__ lo)
{
    int i = blockIdx.x * blockDim.x + threadIdx.x;   // over SEQ*KVD/4
    if (i >= SEQ * KVD / 4) return;
    int row = i / (KVD / 4), c4 = i - row * (KVD / 4);
    float4 v = *(const float4*)(qkv + (size_t)row * QKVD + DIM + KVD + c4 * 4);
    __nv_bfloat16 h0 = __float2bfloat16(v.x);
    __nv_bfloat16 h1 = __float2bfloat16(v.y);
    __nv_bfloat16 h2 = __float2bfloat16(v.z);
    __nv_bfloat16 h3 = __float2bfloat16(v.w);
    size_t o = (size_t)row * KVD + c4 * 4;
    __nv_bfloat162 a; a.x = h0; a.y = h1; *(__nv_bfloat162*)(hi + o) = a;
    __nv_bfloat162 b; b.x = h2; b.y = h3; *(__nv_bfloat162*)(hi + o + 2) = b;
    __nv_bfloat162 c;
    c.x = __float2bfloat16(v.x - __bfloat162float(h0));
    c.y = __float2bfloat16(v.y - __bfloat162float(h1));
    *(__nv_bfloat162*)(lo + o) = c;
    __nv_bfloat162 d;
    d.x = __float2bfloat16(v.z - __bfloat162float(h2));
    d.y = __float2bfloat16(v.w - __bfloat162float(h3));
    *(__nv_bfloat162*)(lo + o + 2) = d;
}

// ---------------- tensor-core flash attention (R5-proven; fp16 output) --------
#define AROWB 272
#define QT_B  (128 * AROWB)
#define KT_B  (64 * AROWB)
#define KVBUF (4 * KT_B)
#define ATT_SMEM (2 * QT_B + 2 * KVBUF)

__global__ __launch_bounds__(256) void attn_tc(
    const __nv_bfloat16* __restrict__ Qh, const __nv_bfloat16* __restrict__ Ql,
    const __nv_bfloat16* __restrict__ Kh, const __nv_bfloat16* __restrict__ Kl,
    const __nv_bfloat16* __restrict__ Vh, const __nv_bfloat16* __restrict__ Vl,
    __half* __restrict__ O)
{
    extern __shared__ char smc[];
    const uint32_t sb  = smem_u32(smc);
    const int t = threadIdx.x, lane = t & 31, w = t >> 5;
    const int h = blockIdx.y, q0 = blockIdx.x << 7, kvh = h >> 2;

    const uint32_t sQh = sb;
    const uint32_t sQl = sb + QT_B;
    const uint32_t sKV = sb + 2 * QT_B;

    {
        const __nv_bfloat16* qs[2] = { Qh, Ql };
        uint32_t qd[2] = { sQh, sQl };
#pragma unroll
        for (int tn = 0; tn < 2; tn++)
#pragma unroll
            for (int p = 0; p < 8; p++) {
                int chunk = t + p * 256;
                int row = chunk >> 4, c = chunk & 15;
                CP_ASYNC16(qd[tn] + row * AROWB + c * 16,
                           qs[tn] + (size_t)(q0 + row) * DIM + h * HD + c * 8);
            }
    }
    const __nv_bfloat16* kvsrc[4] = { Kh, Kl, Vh, Vl };
#pragma unroll
    for (int tn = 0; tn < 4; tn++)
#pragma unroll
        for (int p = 0; p < 4; p++) {
            int chunk = t + p * 256;
            int row = chunk >> 4, c = chunk & 15;
            CP_ASYNC16(sKV + tn * KT_B + row * AROWB + c * 16,
                       kvsrc[tn] + (size_t)row * KVD + kvh * HD + c * 8);
        }
    CP_COMMIT();

    float m0 = -INFINITY, m1 = -INFINITY, l0 = 0.f, l1 = 0.f;
    float oacc[16][4];
#pragma unroll
    for (int i = 0; i < 16; i++)
#pragma unroll
        for (int j = 0; j < 4; j++) oacc[i][j] = 0.f;

    const int NIT = SEQ / 64;
    for (int it = 0; it < NIT; it++) {
        CP_WAIT(0);
        __syncthreads();
        const uint32_t kvb = sKV + (it & 1) * KVBUF;
        if (it + 1 < NIT) {
            const uint32_t nb = sKV + ((it + 1) & 1) * KVBUF;
            const int k0n = (it + 1) * 64;
#pragma unroll
            for (int tn = 0; tn < 4; tn++)
#pragma unroll
                for (int p = 0; p < 4; p++) {
                    int chunk = t + p * 256;
                    int row = chunk >> 4, c = chunk & 15;
                    CP_ASYNC16(nb + tn * KT_B + row * AROWB + c * 16,
                               kvsrc[tn] + (size_t)(k0n + row) * KVD + kvh * HD + c * 8);
                }
            CP_COMMIT();
        }

        float sacc[8][4];
#pragma unroll
        for (int i = 0; i < 8; i++)
#pragma unroll
            for (int j = 0; j < 4; j++) sacc[i][j] = 0.f;

#pragma unroll
        for (int ks = 0; ks < 8; ks++) {
            const uint32_t aoff = (uint32_t)(16 * w + (lane & 15)) * AROWB
                                + ks * 32 + (lane >> 4) * 16;
            uint32_t ah[4], al[4];
            LDSM_X4(ah, sQh + aoff);
            LDSM_X4(al, sQl + aoff);
#pragma unroll
            for (int g = 0; g < 4; g++) {
                const uint32_t boff = (uint32_t)(g * 16 + (lane & 15)) * AROWB
                                    + ks * 32 + (lane >> 4) * 16;
                uint32_t bh[4], bl[4];
                LDSM_X4(bh, kvb + boff);
                LDSM_X4(bl, kvb + KT_B + boff);
#pragma unroll
                for (int sel = 0; sel < 2; sel++) {
                    MMA_BF16(sacc[2 * g + sel], ah, bh[sel], bh[sel + 2]);
                    MMA_BF16(sacc[2 * g + sel], ah, bl[sel], bl[sel + 2]);
                    MMA_BF16(sacc[2 * g + sel], al, bh[sel], bh[sel + 2]);
                }
            }
        }

        float mc0 = -INFINITY, mc1 = -INFINITY;
#pragma unroll
        for (int i = 0; i < 8; i++) {
            mc0 = fmaxf(mc0, fmaxf(sacc[i][0], sacc[i][1]));
            mc1 = fmaxf(mc1, fmaxf(sacc[i][2], sacc[i][3]));
        }
        mc0 = fmaxf(mc0, __shfl_xor_sync(0xffffffffu, mc0, 1));
        mc0 = fmaxf(mc0, __shfl_xor_sync(0xffffffffu, mc0, 2));
        mc1 = fmaxf(mc1, __shfl_xor_sync(0xffffffffu, mc1, 1));
        mc1 = fmaxf(mc1, __shfl_xor_sync(0xffffffffu, mc1, 2));
        const float mn0 = fmaxf(m0, mc0), mn1 = fmaxf(m1, mc1);
        const float alpha0 = __expf(m0 - mn0), alpha1 = __expf(m1 - mn1);
        m0 = mn0; m1 = mn1;
        float sum0 = 0.f, sum1 = 0.f;
#pragma unroll
        for (int i = 0; i < 8; i++) {
            sacc[i][0] = __expf(sacc[i][0] - mn0);
            sacc[i][1] = __expf(sacc[i][1] - mn0);
            sacc[i][2] = __expf(sacc[i][2] - mn1);
            sacc[i][3] = __expf(sacc[i][3] - mn1);
            sum0 += sacc[i][0] + sacc[i][1];
            sum1 += sacc[i][2] + sacc[i][3];
        }
        sum0 += __shfl_xor_sync(0xffffffffu, sum0, 1);
        sum0 += __shfl_xor_sync(0xffffffffu, sum0, 2);
        sum1 += __shfl_xor_sync(0xffffffffu, sum1, 1);
        sum1 += __shfl_xor_sync(0xffffffffu, sum1, 2);
        l0 = l0 * alpha0 + sum0;
        l1 = l1 * alpha1 + sum1;

#pragma unroll
        for (int i = 0; i < 16; i++) {
            oacc[i][0] *= alpha0; oacc[i][1] *= alpha0;
            oacc[i][2] *= alpha1; oacc[i][3] *= alpha1;
        }

        uint32_t pah[4][4], pal[4][4];
#pragma unroll
        for (int ks = 0; ks < 4; ks++) {
#pragma unroll
            for (int half = 0; half < 2; half++) {
                const int nt = 2 * ks + half;
                float e0 = sacc[nt][0], e1 = sacc[nt][1];
                float e2 = sacc[nt][2], e3 = sacc[nt][3];
                __nv_bfloat16 h0 = __float2bfloat16(e0);
                __nv_bfloat16 h1 = __float2bfloat16(e1);
                __nv_bfloat16 h2 = __float2bfloat16(e2);
                __nv_bfloat16 h3 = __float2bfloat16(e3);
                pah[ks][2 * half + 0] = pack_bf16x2(e0, e1);
                pah[ks][2 * half + 1] = pack_bf16x2(e2, e3);
                pal[ks][2 * half + 0] = pack_bf16x2(e0 - __bfloat162float(h0),
                                                    e1 - __bfloat162float(h1));
                pal[ks][2 * half + 1] = pack_bf16x2(e2 - __bfloat162float(h2),
                                                    e3 - __bfloat162float(h3));
            }
        }

#pragma unroll
        for (int ks = 0; ks < 4; ks++) {
#pragma unroll
            for (int g = 0; g < 8; g++) {
                const uint32_t voff = (uint32_t)(ks * 16 + (lane & 15)) * AROWB
                                    + (g * 16 + (lane >> 4) * 8) * 2;
                uint32_t vh[4], vl[4];
                LDSM_X4_T(vh, kvb + 2 * KT_B + voff);
                LDSM_X4_T(vl, kvb + 3 * KT_B + voff);
#pragma unroll
                for (int sel = 0; sel < 2; sel++) {
                    MMA_BF16(oacc[2 * g + sel], pah[ks], vh[2 * sel], vh[2 * sel + 1]);
                    MMA_BF16(oacc[2 * g + sel], pah[ks], vl[2 * sel], vl[2 * sel + 1]);
                    MMA_BF16(oacc[2 * g + sel], pal[ks], vh[2 * sel], vh[2 * sel + 1]);
                }
            }
        }
    }

    const float inv0 = 1.0f / l0, inv1 = 1.0f / l1;
    const int r0 = q0 + 16 * w + (lane >> 2);
    const int r1 = r0 + 8;
#pragma unroll
    for (int nt = 0; nt < 16; nt++) {
        const int col = h * HD + nt * 8 + (lane & 3) * 2;
        *(__half2*)(O + (size_t)r0 * DIM + col) =
            __floats2half2_rn(oacc[nt][0] * inv0, oacc[nt][1] * inv0);
        *(__half2*)(O + (size_t)r1 * DIM + col) =
            __floats2half2_rn(oacc[nt][2] * inv1, oacc[nt][3] * inv1);
    }
}

// ---------------- launch -------------------------------------------------------
extern "C" void kernel_launch(void* const* d_in, const int* in_sizes, int n_in,
                              void* d_out, int out_size)
{
    const float* x  = (const float*)d_in[0];
    const float* fc = (const float*)d_in[1];
    const float* fs = (const float*)d_in[2];
    const float* wq = (const float*)d_in[3];
    const float* wk = (const float*)d_in[4];
    const float* wv = (const float*)d_in[5];
    const float* wo = (const float*)d_in[6];
    float* out = (float*)d_out;

    float* qkv;
    cudaGetSymbolAddress((void**)&qkv, g_qkv);

    __half *xh, *atth, *wqkvT, *woT;
    cudaGetSymbolAddress((void**)&xh,    g_xh);
    cudaGetSymbolAddress((void**)&atth,  g_atth);
    cudaGetSymbolAddress((void**)&wqkvT, g_wqkvT);
    cudaGetSymbolAddress((void**)&woT,   g_woT);

    __nv_bfloat16 *qsh, *qsl, *ksh, *ksl, *vsh, *vsl;
    cudaGetSymbolAddress((void**)&qsh, g_qs_hi); cudaGetSymbolAddress((void**)&qsl, g_qs_lo);
    cudaGetSymbolAddress((void**)&ksh, g_ks_hi); cudaGetSymbolAddress((void**)&ksl, g_ks_lo);
    cudaGetSymbolAddress((void**)&vsh, g_vs_hi); cudaGetSymbolAddress((void**)&vsl, g_vs_lo);

    cudaFuncSetAttribute(gemm_h,
                         cudaFuncAttributeMaxDynamicSharedMemorySize, GEMM_SMEM);
    cudaFuncSetAttribute(attn_tc,
                         cudaFuncAttributeMaxDynamicSharedMemorySize, ATT_SMEM);

    // launches 1-4: convert x + q/k/v weights (wk/wv rows appended in wqkvT)
    hconv_kernel<<<(SEQ * DIM / 4 + 255) / 256, 256>>>(x, xh, SEQ * DIM / 4);
    tconv_kernel<<<dim3(DIM / 32, DIM / 32), dim3(32, 8)>>>(wq, wqkvT, DIM, DIM);
    tconv_kernel<<<dim3(KVD / 32, DIM / 32), dim3(32, 8)>>>(
        wk, wqkvT + (size_t)DIM * DIM, DIM, KVD);
    tconv_kernel<<<dim3(KVD / 32, DIM / 32), dim3(32, 8)>>>(
        wv, wqkvT + (size_t)(DIM + KVD) * DIM, DIM, KVD);

    // launch 5: merged QKV projection (profiled by ncu)
    gemm_h<<<dim3(QKVD / 256, SEQ / 128), 256, GEMM_SMEM>>>(
        xh, wqkvT, qkv, SEQ, QKVD, DIM);

    // remaining prep + attention + O-projection
    tconv_kernel<<<dim3(DIM / 32, DIM / 32), dim3(32, 8)>>>(wo, woT, DIM, DIM);

    int nrope = SEQ * (NH + NKV) * (HD / 2);
    rope_split_kernel<<<(nrope + 255) / 256, 256>>>(qkv, fc, fs, qsh, qsl, ksh, ksl);
    vsplit_kernel<<<(SEQ * KVD / 4 + 255) / 256, 256>>>(qkv, vsh, vsl);

    attn_tc<<<dim3(SEQ / 128, NH), 256, ATT_SMEM>>>(qsh, qsl, ksh, ksl, vsh, vsl, atth);

    gemm_h<<<dim3(DIM / 256, SEQ / 128), 256, GEMM_SMEM>>>(atth, woT, out, SEQ, DIM, DIM);
}

// round 9
// speedup vs baseline: 4.2626x; 1.0013x over previous
#include <cuda_runtime.h>
#include <cuda_bf16.h>
#include <cuda_fp16.h>
#include <math.h>
#include <stdint.h>

#define SEQ   2048
#define DIM   4096
#define NH    32
#define NKV   8
#define HD    128
#define KVD   1024
#define QKVD  6144          // DIM + 2*KVD (merged q|k|v output)
#define SCALE 0.08838834764831845f

// ---------------- scratch ----------------------------------------------------
__device__ float g_qkv[SEQ * QKVD];        // merged q|k|v projection output

__device__ __half g_xh[SEQ * DIM];
__device__ __half g_atth[SEQ * DIM];
__device__ __half g_wqkvT[QKVD * DIM];     // [wq^T ; wk^T ; wv^T] rows
__device__ __half g_woT[DIM * DIM];

// bf16 split Q/K/V for attention (Q pre-scaled, RoPE applied)
__device__ __nv_bfloat16 g_qs_hi[SEQ * DIM], g_qs_lo[SEQ * DIM];
__device__ __nv_bfloat16 g_ks_hi[SEQ * KVD], g_ks_lo[SEQ * KVD];
__device__ __nv_bfloat16 g_vs_hi[SEQ * KVD], g_vs_lo[SEQ * KVD];

// ---------------- PTX helpers (baseline PTX only) -----------------------------
__device__ __forceinline__ uint32_t smem_u32(const void* p) {
    uint32_t a;
    asm("{ .reg .u64 t; cvta.to.shared.u64 t, %1; cvt.u32.u64 %0, t; }"
        : "=r"(a) : "l"(p));
    return a;
}
#define CP_ASYNC16(dst, src) \
    asm volatile("cp.async.cg.shared.global [%0], [%1], 16;" :: "r"(dst), "l"(src) : "memory")
#define CP_COMMIT()  asm volatile("cp.async.commit_group;" ::: "memory")
#define CP_WAIT(n)   asm volatile("cp.async.wait_group %0;" :: "n"(n) : "memory")

#define LDSM_X4(r, addr)                                                      \
    asm volatile("ldmatrix.sync.aligned.m8n8.x4.shared.b16 {%0,%1,%2,%3}, [%4];" \
        : "=r"((r)[0]), "=r"((r)[1]), "=r"((r)[2]), "=r"((r)[3]) : "r"(addr))
#define LDSM_X4_T(r, addr)                                                    \
    asm volatile("ldmatrix.sync.aligned.m8n8.x4.trans.shared.b16 {%0,%1,%2,%3}, [%4];" \
        : "=r"((r)[0]), "=r"((r)[1]), "=r"((r)[2]), "=r"((r)[3]) : "r"(addr))

#define MMA_BF16(d, a, b0, b1)                                                \
    asm volatile("mma.sync.aligned.m16n8k16.row.col.f32.bf16.bf16.f32 "       \
        "{%0,%1,%2,%3}, {%4,%5,%6,%7}, {%8,%9}, {%0,%1,%2,%3};"               \
        : "+f"((d)[0]), "+f"((d)[1]), "+f"((d)[2]), "+f"((d)[3])              \
        : "r"((a)[0]), "r"((a)[1]), "r"((a)[2]), "r"((a)[3]), "r"(b0), "r"(b1))

#define MMA_F16(d, a, b0, b1)                                                 \
    asm volatile("mma.sync.aligned.m16n8k16.row.col.f32.f16.f16.f32 "         \
        "{%0,%1,%2,%3}, {%4,%5,%6,%7}, {%8,%9}, {%0,%1,%2,%3};"               \
        : "+f"((d)[0]), "+f"((d)[1]), "+f"((d)[2]), "+f"((d)[3])              \
        : "r"((a)[0]), "r"((a)[1]), "r"((a)[2]), "r"((a)[3]), "r"(b0), "r"(b1))

__device__ __forceinline__ uint32_t pack_bf16x2(float lo, float hi) {
    __nv_bfloat162 p = __float22bfloat162_rn(make_float2(lo, hi));
    return *(uint32_t*)&p;
}

// ---------------- fp32 -> fp16 convert (elementwise) ---------------------------
__global__ void hconv_kernel(const float* __restrict__ in,
                             __half* __restrict__ out, int n4)
{
    int i = blockIdx.x * blockDim.x + threadIdx.x;
    if (i >= n4) return;
    float4 v = ((const float4*)in)[i];
    __half2* op = (__half2*)out;
    op[i * 2]     = __floats2half2_rn(v.x, v.y);
    op[i * 2 + 1] = __floats2half2_rn(v.z, v.w);
}

// ---------------- transpose + convert: W[K,N] fp32 -> WT[N,K] fp16 -------------
__global__ void tconv_kernel(const float* __restrict__ B,
                             __half* __restrict__ T, int K, int N)
{
    __shared__ float tile[32][33];
    int n0 = blockIdx.x * 32, k0 = blockIdx.y * 32;
    int tx = threadIdx.x, ty = threadIdx.y;
#pragma unroll
    for (int i = 0; i < 32; i += 8)
        tile[ty + i][tx] = B[(size_t)(k0 + ty + i) * N + n0 + tx];
    __syncthreads();
#pragma unroll
    for (int i = 0; i < 32; i += 8)
        T[(size_t)(n0 + ty + i) * K + k0 + tx] = __float2half_rn(tile[tx][ty + i]);
}

// ---------------- fp16 mma.sync GEMM: C[M,N] = A[M,K] @ B[N,K]^T ---------------
// CTA tile 128x256, BK=32, 8 warps 2x4 -> warp tile 64x64 (4x8 mma tiles).
#define BK     32
#define ASTR   40                       // smem row stride (halves)
#define A_E    (128 * ASTR)             // A tile: 5120 halves
#define B_E    (256 * ASTR)             // B tile: 10240 halves
#define BUF_E  (A_E + B_E)
#define GEMM_SMEM (2 * BUF_E * 2)       // 61440 bytes

__global__ __launch_bounds__(256, 1) void gemm_h(
    const __half* __restrict__ A, const __half* __restrict__ B,
    float* __restrict__ C, int M, int N, int K)
{
    extern __shared__ __half smh[];
    const uint32_t sbase = smem_u32(smh);
    const int t = threadIdx.x, lane = t & 31, w = t >> 5;
    const int wm = w & 1, wn = w >> 1;           // 2 x 4 warp grid
    const int m0 = blockIdx.y << 7, n0 = blockIdx.x << 8;

    const __half* srcA = A + (size_t)m0 * K;
    const __half* srcB = B + (size_t)n0 * K;

    float acc[4][8][4];
#pragma unroll
    for (int a = 0; a < 4; a++)
#pragma unroll
        for (int b = 0; b < 8; b++)
#pragma unroll
            for (int c = 0; c < 4; c++) acc[a][b][c] = 0.f;

    const int lr = t >> 2, lc = (t & 3) * 8;     // load row / col chunk (halves)

    // prologue: buffer 0
    {
        uint32_t dA = sbase;
        uint32_t dB = sbase + A_E * 2;
        CP_ASYNC16(dA + (lr * ASTR + lc) * 2,        srcA + (size_t)lr * K + lc);
        CP_ASYNC16(dA + ((lr + 64) * ASTR + lc) * 2, srcA + (size_t)(lr + 64) * K + lc);
#pragma unroll
        for (int rr = 0; rr < 4; rr++)
            CP_ASYNC16(dB + ((lr + rr * 64) * ASTR + lc) * 2,
                       srcB + (size_t)(lr + rr * 64) * K + lc);
    }
    CP_COMMIT();

    const int niter = K / BK;
    for (int i = 0; i < niter; i++) {
        const int b = i & 1;
        if (i + 1 < niter) {
            const int nb = b ^ 1;
            const size_t koff = (size_t)(i + 1) * BK;
            uint32_t dA = sbase + (uint32_t)(nb * BUF_E) * 2;
            uint32_t dB = dA + A_E * 2;
            CP_ASYNC16(dA + (lr * ASTR + lc) * 2,        srcA + (size_t)lr * K + koff + lc);
            CP_ASYNC16(dA + ((lr + 64) * ASTR + lc) * 2, srcA + (size_t)(lr + 64) * K + koff + lc);
#pragma unroll
            for (int rr = 0; rr < 4; rr++)
                CP_ASYNC16(dB + ((lr + rr * 64) * ASTR + lc) * 2,
                           srcB + (size_t)(lr + rr * 64) * K + koff + lc);
            CP_COMMIT();
            CP_WAIT(1);
        } else {
            CP_WAIT(0);
        }
        __syncthreads();

        const uint32_t As = sbase + (uint32_t)(b * BUF_E) * 2;
        const uint32_t Bs = As + A_E * 2;

#pragma unroll
        for (int ks = 0; ks < 2; ks++) {
            const int koff = ks * 16 + (lane >> 4) * 8;
            const int arow = wm * 64 + (lane & 15);
            const int brow = wn * 64 + (lane & 15);

            uint32_t af[4][4], bf[4][4];
#pragma unroll
            for (int mt = 0; mt < 4; mt++)
                LDSM_X4(af[mt], As + (uint32_t)((arow + mt * 16) * ASTR + koff) * 2);
#pragma unroll
            for (int np = 0; np < 4; np++)
                LDSM_X4(bf[np], Bs + (uint32_t)((brow + np * 16) * ASTR + koff) * 2);
#pragma unroll
            for (int mt = 0; mt < 4; mt++)
#pragma unroll
                for (int nt = 0; nt < 8; nt++) {
                    const int np = nt >> 1, sel = nt & 1;
                    MMA_F16(acc[mt][nt], af[mt], bf[np][sel], bf[np][sel + 2]);
                }
        }
        __syncthreads();
    }

#pragma unroll
    for (int mt = 0; mt < 4; mt++) {
        const int r = m0 + wm * 64 + mt * 16 + (lane >> 2);
#pragma unroll
        for (int nt = 0; nt < 8; nt++) {
            const int c = n0 + wn * 64 + nt * 8 + (lane & 3) * 2;
            *(float2*)(C + (size_t)r * N + c) =
                make_float2(acc[mt][nt][0], acc[mt][nt][1]);
            *(float2*)(C + (size_t)(r + 8) * N + c) =
                make_float2(acc[mt][nt][2], acc[mt][nt][3]);
        }
    }
}

// ---------------- fused RoPE + scale + bf16 split (reads merged qkv) ----------
__global__ void rope_split_kernel(
    const float* __restrict__ qkv,
    const float* __restrict__ fc, const float* __restrict__ fs,
    __nv_bfloat16* __restrict__ qh, __nv_bfloat16* __restrict__ ql,
    __nv_bfloat16* __restrict__ kh, __nv_bfloat16* __restrict__ kl)
{
    int idx = blockIdx.x * blockDim.x + threadIdx.x;
    const int qn = SEQ * NH * (HD / 2);
    const int kn = SEQ * NKV * (HD / 2);
    float o1, o2;
    size_t off_out;
    __nv_bfloat16 *ph, *pl;
    if (idx < qn) {
        int s = idx / (NH * 64);
        int rem = idx - s * (NH * 64);
        int h = rem >> 6, i = rem & 63;
        float c = fc[s * 64 + i], sn = fs[s * 64 + i];
        size_t off_in = (size_t)s * QKVD + h * HD + 2 * i;
        float t1 = qkv[off_in], t2 = qkv[off_in + 1];
        o1 = (t1 * c - t2 * sn) * SCALE;
        o2 = (t1 * sn + t2 * c) * SCALE;
        off_out = (size_t)s * DIM + h * HD + 2 * i;
        ph = qh; pl = ql;
    } else if (idx < qn + kn) {
        int j = idx - qn;
        int s = j / (NKV * 64);
        int rem = j - s * (NKV * 64);
        int h = rem >> 6, i = rem & 63;
        float c = fc[s * 64 + i], sn = fs[s * 64 + i];
        size_t off_in = (size_t)s * QKVD + DIM + h * HD + 2 * i;
        float t1 = qkv[off_in], t2 = qkv[off_in + 1];
        o1 = t1 * c - t2 * sn;
        o2 = t1 * sn + t2 * c;
        off_out = (size_t)s * KVD + h * HD + 2 * i;
        ph = kh; pl = kl;
    } else return;
    __nv_bfloat16 h1 = __float2bfloat16(o1);
    __nv_bfloat16 h2 = __float2bfloat16(o2);
    __nv_bfloat162 hp; hp.x = h1; hp.y = h2;
    __nv_bfloat162 lp;
    lp.x = __float2bfloat16(o1 - __bfloat162float(h1));
    lp.y = __float2bfloat16(o2 - __bfloat162float(h2));
    *(__nv_bfloat162*)(ph + off_out) = hp;
    *(__nv_bfloat162*)(pl + off_out) = lp;
}

// ---------------- strided split fp32 -> bf16 hi/lo (V from merged qkv) --------
__global__ void vsplit_kernel(const float* __restrict__ qkv,
                              __nv_bfloat16* __restrict__ hi,
                              __nv_bfloat16* __restrict__ lo)
{
    int i = blockIdx.x * blockDim.x + threadIdx.x;   // over SEQ*KVD/4
    if (i >= SEQ * KVD / 4) return;
    int row = i / (KVD / 4), c4 = i - row * (KVD / 4);
    float4 v = *(const float4*)(qkv + (size_t)row * QKVD + DIM + KVD + c4 * 4);
    __nv_bfloat16 h0 = __float2bfloat16(v.x);
    __nv_bfloat16 h1 = __float2bfloat16(v.y);
    __nv_bfloat16 h2 = __float2bfloat16(v.z);
    __nv_bfloat16 h3 = __float2bfloat16(v.w);
    size_t o = (size_t)row * KVD + c4 * 4;
    __nv_bfloat162 a; a.x = h0; a.y = h1; *(__nv_bfloat162*)(hi + o) = a;
    __nv_bfloat162 b; b.x = h2; b.y = h3; *(__nv_bfloat162*)(hi + o + 2) = b;
    __nv_bfloat162 c;
    c.x = __float2bfloat16(v.x - __bfloat162float(h0));
    c.y = __float2bfloat16(v.y - __bfloat162float(h1));
    *(__nv_bfloat162*)(lo + o) = c;
    __nv_bfloat162 d;
    d.x = __float2bfloat16(v.z - __bfloat162float(h2));
    d.y = __float2bfloat16(v.w - __bfloat162float(h3));
    *(__nv_bfloat162*)(lo + o + 2) = d;
}

// ---------------- tensor-core flash attention (R5-proven; fp16 output) --------
#define AROWB 272
#define QT_B  (128 * AROWB)
#define KT_B  (64 * AROWB)
#define KVBUF (4 * KT_B)
#define ATT_SMEM (2 * QT_B + 2 * KVBUF)

__global__ __launch_bounds__(256) void attn_tc(
    const __nv_bfloat16* __restrict__ Qh, const __nv_bfloat16* __restrict__ Ql,
    const __nv_bfloat16* __restrict__ Kh, const __nv_bfloat16* __restrict__ Kl,
    const __nv_bfloat16* __restrict__ Vh, const __nv_bfloat16* __restrict__ Vl,
    __half* __restrict__ O)
{
    extern __shared__ char smc[];
    const uint32_t sb  = smem_u32(smc);
    const int t = threadIdx.x, lane = t & 31, w = t >> 5;
    const int h = blockIdx.y, q0 = blockIdx.x << 7, kvh = h >> 2;

    const uint32_t sQh = sb;
    const uint32_t sQl = sb + QT_B;
    const uint32_t sKV = sb + 2 * QT_B;

    {
        const __nv_bfloat16* qs[2] = { Qh, Ql };
        uint32_t qd[2] = { sQh, sQl };
#pragma unroll
        for (int tn = 0; tn < 2; tn++)
#pragma unroll
            for (int p = 0; p < 8; p++) {
                int chunk = t + p * 256;
                int row = chunk >> 4, c = chunk & 15;
                CP_ASYNC16(qd[tn] + row * AROWB + c * 16,
                           qs[tn] + (size_t)(q0 + row) * DIM + h * HD + c * 8);
            }
    }
    const __nv_bfloat16* kvsrc[4] = { Kh, Kl, Vh, Vl };
#pragma unroll
    for (int tn = 0; tn < 4; tn++)
#pragma unroll
        for (int p = 0; p < 4; p++) {
            int chunk = t + p * 256;
            int row = chunk >> 4, c = chunk & 15;
            CP_ASYNC16(sKV + tn * KT_B + row * AROWB + c * 16,
                       kvsrc[tn] + (size_t)row * KVD + kvh * HD + c * 8);
        }
    CP_COMMIT();

    float m0 = -INFINITY, m1 = -INFINITY, l0 = 0.f, l1 = 0.f;
    float oacc[16][4];
#pragma unroll
    for (int i = 0; i < 16; i++)
#pragma unroll
        for (int j = 0; j < 4; j++) oacc[i][j] = 0.f;

    const int NIT = SEQ / 64;
    for (int it = 0; it < NIT; it++) {
        CP_WAIT(0);
        __syncthreads();
        const uint32_t kvb = sKV + (it & 1) * KVBUF;
        if (it + 1 < NIT) {
            const uint32_t nb = sKV + ((it + 1) & 1) * KVBUF;
            const int k0n = (it + 1) * 64;
#pragma unroll
            for (int tn = 0; tn < 4; tn++)
#pragma unroll
                for (int p = 0; p < 4; p++) {
                    int chunk = t + p * 256;
                    int row = chunk >> 4, c = chunk & 15;
                    CP_ASYNC16(nb + tn * KT_B + row * AROWB + c * 16,
                               kvsrc[tn] + (size_t)(k0n + row) * KVD + kvh * HD + c * 8);
                }
            CP_COMMIT();
        }

        float sacc[8][4];
#pragma unroll
        for (int i = 0; i < 8; i++)
#pragma unroll
            for (int j = 0; j < 4; j++) sacc[i][j] = 0.f;

#pragma unroll
        for (int ks = 0; ks < 8; ks++) {
            const uint32_t aoff = (uint32_t)(16 * w + (lane & 15)) * AROWB
                                + ks * 32 + (lane >> 4) * 16;
            uint32_t ah[4], al[4];
            LDSM_X4(ah, sQh + aoff);
            LDSM_X4(al, sQl + aoff);
#pragma unroll
            for (int g = 0; g < 4; g++) {
                const uint32_t boff = (uint32_t)(g * 16 + (lane & 15)) * AROWB
                                    + ks * 32 + (lane >> 4) * 16;
                uint32_t bh[4], bl[4];
                LDSM_X4(bh, kvb + boff);
                LDSM_X4(bl, kvb + KT_B + boff);
#pragma unroll
                for (int sel = 0; sel < 2; sel++) {
                    MMA_BF16(sacc[2 * g + sel], ah, bh[sel], bh[sel + 2]);
                    MMA_BF16(sacc[2 * g + sel], ah, bl[sel], bl[sel + 2]);
                    MMA_BF16(sacc[2 * g + sel], al, bh[sel], bh[sel + 2]);
                }
            }
        }

        float mc0 = -INFINITY, mc1 = -INFINITY;
#pragma unroll
        for (int i = 0; i < 8; i++) {
            mc0 = fmaxf(mc0, fmaxf(sacc[i][0], sacc[i][1]));
            mc1 = fmaxf(mc1, fmaxf(sacc[i][2], sacc[i][3]));
        }
        mc0 = fmaxf(mc0, __shfl_xor_sync(0xffffffffu, mc0, 1));
        mc0 = fmaxf(mc0, __shfl_xor_sync(0xffffffffu, mc0, 2));
        mc1 = fmaxf(mc1, __shfl_xor_sync(0xffffffffu, mc1, 1));
        mc1 = fmaxf(mc1, __shfl_xor_sync(0xffffffffu, mc1, 2));
        const float mn0 = fmaxf(m0, mc0), mn1 = fmaxf(m1, mc1);
        const float alpha0 = __expf(m0 - mn0), alpha1 = __expf(m1 - mn1);
        m0 = mn0; m1 = mn1;
        float sum0 = 0.f, sum1 = 0.f;
#pragma unroll
        for (int i = 0; i < 8; i++) {
            sacc[i][0] = __expf(sacc[i][0] - mn0);
            sacc[i][1] = __expf(sacc[i][1] - mn0);
            sacc[i][2] = __expf(sacc[i][2] - mn1);
            sacc[i][3] = __expf(sacc[i][3] - mn1);
            sum0 += sacc[i][0] + sacc[i][1];
            sum1 += sacc[i][2] + sacc[i][3];
        }
        sum0 += __shfl_xor_sync(0xffffffffu, sum0, 1);
        sum0 += __shfl_xor_sync(0xffffffffu, sum0, 2);
        sum1 += __shfl_xor_sync(0xffffffffu, sum1, 1);
        sum1 += __shfl_xor_sync(0xffffffffu, sum1, 2);
        l0 = l0 * alpha0 + sum0;
        l1 = l1 * alpha1 + sum1;

#pragma unroll
        for (int i = 0; i < 16; i++) {
            oacc[i][0] *= alpha0; oacc[i][1] *= alpha0;
            oacc[i][2] *= alpha1; oacc[i][3] *= alpha1;
        }

        uint32_t pah[4][4], pal[4][4];
#pragma unroll
        for (int ks = 0; ks < 4; ks++) {
#pragma unroll
            for (int half = 0; half < 2; half++) {
                const int nt = 2 * ks + half;
                float e0 = sacc[nt][0], e1 = sacc[nt][1];
                float e2 = sacc[nt][2], e3 = sacc[nt][3];
                __nv_bfloat16 h0 = __float2bfloat16(e0);
                __nv_bfloat16 h1 = __float2bfloat16(e1);
                __nv_bfloat16 h2 = __float2bfloat16(e2);
                __nv_bfloat16 h3 = __float2bfloat16(e3);
                pah[ks][2 * half + 0] = pack_bf16x2(e0, e1);
                pah[ks][2 * half + 1] = pack_bf16x2(e2, e3);
                pal[ks][2 * half + 0] = pack_bf16x2(e0 - __bfloat162float(h0),
                                                    e1 - __bfloat162float(h1));
                pal[ks][2 * half + 1] = pack_bf16x2(e2 - __bfloat162float(h2),
                                                    e3 - __bfloat162float(h3));
            }
        }

#pragma unroll
        for (int ks = 0; ks < 4; ks++) {
#pragma unroll
            for (int g = 0; g < 8; g++) {
                const uint32_t voff = (uint32_t)(ks * 16 + (lane & 15)) * AROWB
                                    + (g * 16 + (lane >> 4) * 8) * 2;
                uint32_t vh[4], vl[4];
                LDSM_X4_T(vh, kvb + 2 * KT_B + voff);
                LDSM_X4_T(vl, kvb + 3 * KT_B + voff);
#pragma unroll
                for (int sel = 0; sel < 2; sel++) {
                    MMA_BF16(oacc[2 * g + sel], pah[ks], vh[2 * sel], vh[2 * sel + 1]);
                    MMA_BF16(oacc[2 * g + sel], pah[ks], vl[2 * sel], vl[2 * sel + 1]);
                    MMA_BF16(oacc[2 * g + sel], pal[ks], vh[2 * sel], vh[2 * sel + 1]);
                }
            }
        }
    }

    const float inv0 = 1.0f / l0, inv1 = 1.0f / l1;
    const int r0 = q0 + 16 * w + (lane >> 2);
    const int r1 = r0 + 8;
#pragma unroll
    for (int nt = 0; nt < 16; nt++) {
        const int col = h * HD + nt * 8 + (lane & 3) * 2;
        *(__half2*)(O + (size_t)r0 * DIM + col) =
            __floats2half2_rn(oacc[nt][0] * inv0, oacc[nt][1] * inv0);
        *(__half2*)(O + (size_t)r1 * DIM + col) =
            __floats2half2_rn(oacc[nt][2] * inv1, oacc[nt][3] * inv1);
    }
}

// ---------------- launch -------------------------------------------------------
extern "C" void kernel_launch(void* const* d_in, const int* in_sizes, int n_in,
                              void* d_out, int out_size)
{
    const float* x  = (const float*)d_in[0];
    const float* fc = (const float*)d_in[1];
    const float* fs = (const float*)d_in[2];
    const float* wq = (const float*)d_in[3];
    const float* wk = (const float*)d_in[4];
    const float* wv = (const float*)d_in[5];
    const float* wo = (const float*)d_in[6];
    float* out = (float*)d_out;

    float* qkv;
    cudaGetSymbolAddress((void**)&qkv, g_qkv);

    __half *xh, *atth, *wqkvT, *woT;
    cudaGetSymbolAddress((void**)&xh,    g_xh);
    cudaGetSymbolAddress((void**)&atth,  g_atth);
    cudaGetSymbolAddress((void**)&wqkvT, g_wqkvT);
    cudaGetSymbolAddress((void**)&woT,   g_woT);

    __nv_bfloat16 *qsh, *qsl, *ksh, *ksl, *vsh, *vsl;
    cudaGetSymbolAddress((void**)&qsh, g_qs_hi); cudaGetSymbolAddress((void**)&qsl, g_qs_lo);
    cudaGetSymbolAddress((void**)&ksh, g_ks_hi); cudaGetSymbolAddress((void**)&ksl, g_ks_lo);
    cudaGetSymbolAddress((void**)&vsh, g_vs_hi); cudaGetSymbolAddress((void**)&vsl, g_vs_lo);

    cudaFuncSetAttribute(gemm_h,
                         cudaFuncAttributeMaxDynamicSharedMemorySize, GEMM_SMEM);
    cudaFuncSetAttribute(attn_tc,
                         cudaFuncAttributeMaxDynamicSharedMemorySize, ATT_SMEM);

    // launches 1-4: convert x + q/k/v weights (wk/wv rows appended in wqkvT)
    hconv_kernel<<<(SEQ * DIM / 4 + 255) / 256, 256>>>(x, xh, SEQ * DIM / 4);
    tconv_kernel<<<dim3(DIM / 32, DIM / 32), dim3(32, 8)>>>(wq, wqkvT, DIM, DIM);
    tconv_kernel<<<dim3(KVD / 32, DIM / 32), dim3(32, 8)>>>(
        wk, wqkvT + (size_t)DIM * DIM, DIM, KVD);
    tconv_kernel<<<dim3(KVD / 32, DIM / 32), dim3(32, 8)>>>(
        wv, wqkvT + (size_t)(DIM + KVD) * DIM, DIM, KVD);

    // launch 5: merged QKV projection (profiled by ncu)
    gemm_h<<<dim3(QKVD / 256, SEQ / 128), 256, GEMM_SMEM>>>(
        xh, wqkvT, qkv, SEQ, QKVD, DIM);

    // remaining prep + attention + O-projection
    tconv_kernel<<<dim3(DIM / 32, DIM / 32), dim3(32, 8)>>>(wo, woT, DIM, DIM);

    int nrope = SEQ * (NH + NKV) * (HD / 2);
    rope_split_kernel<<<(nrope + 255) / 256, 256>>>(qkv, fc, fs, qsh, qsl, ksh, ksl);
    vsplit_kernel<<<(SEQ * KVD / 4 + 255) / 256, 256>>>(qkv, vsh, vsl);

    attn_tc<<<dim3(SEQ / 128, NH), 256, ATT_SMEM>>>(qsh, qsl, ksh, ksl, vsh, vsl, atth);

    gemm_h<<<dim3(DIM / 256, SEQ / 128), 256, GEMM_SMEM>>>(atth, woT, out, SEQ, DIM, DIM);
}